// round 9
// baseline (speedup 1.0000x reference)
#include <cuda_runtime.h>
#include <cuda_fp16.h>
#include <math.h>
#include <cstdint>

#define BB 32
#define CC 3
#define IMGSZ 224
#define NP 14
#define PS 16
#define DIM 768
#define NHD 12
#define HDD 64
#define LL 12
#define NCLS 1000
#define SS 197
#define MLPD 3072
#define RTOT (BB*SS)      /* 6304 rows */
#define PTOT (BB*NP*NP)   /* 6272 patch rows */

// ---------------- scratch (device globals; no allocations) ----------------
__device__ float g_patches[PTOT*DIM];
__device__ float g_x[RTOT*DIM];
__device__ float g_h[RTOT*DIM];
__device__ float g_q[RTOT*DIM];
__device__ float g_k[RTOT*DIM];
__device__ float g_v[RTOT*DIM];
__device__ float g_logits[BB*NCLS];
__device__ __half g_as[(size_t)RTOT*2*MLPD];     // split MLP hidden [M, 2*MLPD]
__device__ __half g_bs[(size_t)RTOT*2*DIM];      // split D-wide activations [M, 2*DIM]
__device__ __half g_ws[(size_t)MLPD*2*DIM];      // split transposed weights [N, 2K] max

#define CP_ASYNC16(dst, src) \
    asm volatile("cp.async.cg.shared.global [%0], [%1], 16;" :: "r"(dst), "l"(src) : "memory")

__device__ __forceinline__ uint32_t smem_u32(const void* p) {
    uint32_t a;
    asm("{ .reg .u64 t; cvta.to.shared.u64 t, %1; cvt.u32.u64 %0, t; }" : "=r"(a) : "l"(p));
    return a;
}

#define MMA16816(c, a, b)                                                        \
    asm volatile("mma.sync.aligned.m16n8k16.row.col.f32.f16.f16.f32 "            \
                 "{%0,%1,%2,%3},{%4,%5,%6,%7},{%8,%9},{%0,%1,%2,%3};"            \
                 : "+f"(c[0]), "+f"(c[1]), "+f"(c[2]), "+f"(c[3])                \
                 : "r"(a[0]), "r"(a[1]), "r"(a[2]), "r"(a[3]), "r"(b[0]), "r"(b[1]));

// ---------------- patchify: (B,C,H,W) -> (B,196,768) ----------------
__global__ void patchify_kernel(const float* __restrict__ img, float* __restrict__ out) {
    int idx = blockIdx.x * blockDim.x + threadIdx.x;
    if (idx >= PTOT * DIM) return;
    int f = idx % DIM;
    int t = (idx / DIM) % (NP * NP);
    int b = idx / (DIM * NP * NP);
    int c  = f >> 8;
    int iy = (f >> 4) & 15;
    int ix = f & 15;
    int py = t / NP, px = t % NP;
    out[idx] = img[(((size_t)b * CC + c) * IMGSZ + py * PS + iy) * IMGSZ + px * PS + ix];
}

// ---------------- assemble x = concat(cls, tokens) + pos ----------------
__global__ void assemble_kernel(const float* __restrict__ tok, const float* __restrict__ cls,
                                const float* __restrict__ pos, float* __restrict__ x) {
    int idx = blockIdx.x * blockDim.x + threadIdx.x;
    if (idx >= RTOT * DIM) return;
    int d = idx % DIM;
    int s = (idx / DIM) % SS;
    int b = idx / (DIM * SS);
    float v = (s == 0) ? cls[d] : tok[((size_t)b * (NP * NP) + (s - 1)) * DIM + d];
    x[idx] = v + pos[s * DIM + d];
}

// ---------------- fp16 split conversions ----------------
__global__ void splitA_kernel(const float* __restrict__ in, __half* __restrict__ out,
                              int M, int K) {
    int i = blockIdx.x * 256 + threadIdx.x;
    int total = (M * K) >> 2;
    if (i >= total) return;
    int e0 = i << 2;
    int m = e0 / K, k = e0 % K;
    float4 v = *(const float4*)(in + e0);
    __half h[4], l[4];
    float vv[4] = {v.x, v.y, v.z, v.w};
#pragma unroll
    for (int j = 0; j < 4; j++) {
        h[j] = __float2half_rn(vv[j]);
        l[j] = __float2half_rn(vv[j] - __half2float(h[j]));
    }
    __half* oh = out + (size_t)m * 2 * K + k;
    *(uint2*)oh         = *(uint2*)h;
    *(uint2*)(oh + K)   = *(uint2*)l;
}

// W: fp32 [K,N] -> fp16 [N,2K] (transpose + split)
__global__ void splitWT_kernel(const float* __restrict__ W, __half* __restrict__ out,
                               int K, int N) {
    __shared__ float t[32][33];
    int n0 = blockIdx.x * 32, k0 = blockIdx.y * 32;
    int tx = threadIdx.x, ty = threadIdx.y;   // 32 x 8
#pragma unroll
    for (int j = 0; j < 32; j += 8)
        t[ty + j][tx] = W[(size_t)(k0 + ty + j) * N + n0 + tx];
    __syncthreads();
#pragma unroll
    for (int j = 0; j < 32; j += 8) {
        float v = t[tx][ty + j];
        __half h = __float2half_rn(v);
        __half l = __float2half_rn(v - __half2float(h));
        size_t base = (size_t)(n0 + ty + j) * 2 * K;
        out[base + k0 + tx]     = h;
        out[base + K + k0 + tx] = l;
    }
}

// ================= fp16 mma.sync 3-pass split GEMM, 128x64 tile, 3 CTAs/SM =================
// MODE 0: Cf = acc+bias (fp32); MODE 1: Ch = split(gelu(acc+bias)) (fp16 [M,2N]);
// MODE 2: Cf += acc+bias (residual)
#define TSTRIDE 80                     /* bytes per smem row */
#define A_TILE_B (128 * TSTRIDE)       /* 10240 B */
#define B_TILE_B (64 * TSTRIDE)        /* 5120 B  */
#define AH_OFF 0
#define AL_OFF A_TILE_B
#define BH_OFF (2 * A_TILE_B)
#define BL_OFF (2 * A_TILE_B + B_TILE_B)
#define STAGE_B (2 * A_TILE_B + 2 * B_TILE_B)   /* 30720 B */
#define NSTAGE 2
#define GEMM_SMEM (NSTAGE * STAGE_B)            /* 61440 B -> 3 CTAs/SM */

template<int MODE>
__global__ __launch_bounds__(256, 3)
void hgemm_kernel(const __half* __restrict__ A, const __half* __restrict__ Bw,
                  const float* __restrict__ bias, float* __restrict__ Cf,
                  __half* __restrict__ Ch, int M, int N, int K) {
    extern __shared__ char smc[];
    uint32_t smb = smem_u32(smc);

    int tid = threadIdx.x, lane = tid & 31, warp = tid >> 5;
    int wm = warp & 1, wn = warp >> 1;          // 2 x 4 warps; warp tile 64 x 16
    int g = lane >> 2, q = lane & 3;
    int row0 = blockIdx.y * 128, col0 = blockIdx.x * 64;
    int K2 = 2 * K;

    float c[4][2][4];
#pragma unroll
    for (int mi = 0; mi < 4; mi++)
#pragma unroll
        for (int ni = 0; ni < 2; ni++)
#pragma unroll
            for (int j = 0; j < 4; j++) c[mi][ni][j] = 0.f;

    auto load_chunk = [&](int ck) {
        uint32_t base = smb + (uint32_t)(ck & 1) * STAGE_B;
        int k0 = ck * 32;
        // A: 128 rows x (hi,lo) x 4 segs = 1024 transfers
#pragma unroll
        for (int j = 0; j < 4; j++) {
            int idx = tid + j * 256;
            int r = idx >> 3, t = idx & 7;
            int tile = t >> 2, seg = t & 3;
            int ga = row0 + r; if (ga >= M) ga = M - 1;
            const __half* src = A + (size_t)ga * K2 + tile * K + k0 + seg * 8;
            CP_ASYNC16(base + AH_OFF + (uint32_t)tile * A_TILE_B + r * TSTRIDE + seg * 16, src);
        }
        // B: 64 rows x (hi,lo) x 4 segs = 512 transfers
#pragma unroll
        for (int j = 0; j < 2; j++) {
            int idx = tid + j * 256;
            int r = idx >> 3, t = idx & 7;
            int tile = t >> 2, seg = t & 3;
            const __half* src = Bw + (size_t)(col0 + r) * K2 + tile * K + k0 + seg * 8;
            CP_ASYNC16(base + BH_OFF + (uint32_t)tile * B_TILE_B + r * TSTRIDE + seg * 16, src);
        }
        asm volatile("cp.async.commit_group;" ::: "memory");
    };

    int nc = K >> 5;
    load_chunk(0);

    for (int ck = 0; ck < nc; ck++) {
        asm volatile("cp.async.wait_group 0;" ::: "memory");   // chunk ck landed
        __syncthreads();                                       // all warps done with old buffer
        if (ck + 1 < nc) load_chunk(ck + 1);                   // overlaps compute of ck

        const char* bufA = smc + (size_t)(ck & 1) * STAGE_B;
#pragma unroll
        for (int kk = 0; kk < 2; kk++) {
            uint32_t ah[4][4], al[4][4], bh[2][2], bl[2][2];
#pragma unroll
            for (int mi = 0; mi < 4; mi++) {
                uint32_t o = (uint32_t)(wm * 64 + mi * 16 + g) * TSTRIDE + kk * 32 + q * 4;
                ah[mi][0] = *(const uint32_t*)(bufA + AH_OFF + o);
                ah[mi][1] = *(const uint32_t*)(bufA + AH_OFF + o + 8 * TSTRIDE);
                ah[mi][2] = *(const uint32_t*)(bufA + AH_OFF + o + 16);
                ah[mi][3] = *(const uint32_t*)(bufA + AH_OFF + o + 8 * TSTRIDE + 16);
                al[mi][0] = *(const uint32_t*)(bufA + AL_OFF + o);
                al[mi][1] = *(const uint32_t*)(bufA + AL_OFF + o + 8 * TSTRIDE);
                al[mi][2] = *(const uint32_t*)(bufA + AL_OFF + o + 16);
                al[mi][3] = *(const uint32_t*)(bufA + AL_OFF + o + 8 * TSTRIDE + 16);
            }
#pragma unroll
            for (int ni = 0; ni < 2; ni++) {
                uint32_t o = (uint32_t)(wn * 16 + ni * 8 + g) * TSTRIDE + kk * 32 + q * 4;
                bh[ni][0] = *(const uint32_t*)(bufA + BH_OFF + o);
                bh[ni][1] = *(const uint32_t*)(bufA + BH_OFF + o + 16);
                bl[ni][0] = *(const uint32_t*)(bufA + BL_OFF + o);
                bl[ni][1] = *(const uint32_t*)(bufA + BL_OFF + o + 16);
            }
#pragma unroll
            for (int mi = 0; mi < 4; mi++)
#pragma unroll
                for (int ni = 0; ni < 2; ni++) {
                    MMA16816(c[mi][ni], ah[mi], bh[ni]);
                    MMA16816(c[mi][ni], ah[mi], bl[ni]);
                    MMA16816(c[mi][ni], al[mi], bh[ni]);
                }
        }
    }

    // ---- epilogue ----
#pragma unroll
    for (int mi = 0; mi < 4; mi++) {
        int r0 = row0 + wm * 64 + mi * 16 + g;
        int r1 = r0 + 8;
#pragma unroll
        for (int ni = 0; ni < 2; ni++) {
            int cI = col0 + wn * 16 + ni * 8 + 2 * q;
            float2 bv = *(const float2*)&bias[cI];
#pragma unroll
            for (int h = 0; h < 2; h++) {
                int r = h ? r1 : r0;
                if (r >= M) continue;
                float v0 = c[mi][ni][h * 2 + 0] + bv.x;
                float v1 = c[mi][ni][h * 2 + 1] + bv.y;
                if (MODE == 1) {
                    v0 = 0.5f * v0 * (1.f + erff(v0 * 0.70710678118654752f));
                    v1 = 0.5f * v1 * (1.f + erff(v1 * 0.70710678118654752f));
                    __half h0 = __float2half_rn(v0);
                    __half h1 = __float2half_rn(v1);
                    __half l0 = __float2half_rn(v0 - __half2float(h0));
                    __half l1 = __float2half_rn(v1 - __half2float(h1));
                    size_t rb = (size_t)r * 2 * N;
                    *(__half2*)&Ch[rb + cI]     = __halves2half2(h0, h1);
                    *(__half2*)&Ch[rb + N + cI] = __halves2half2(l0, l1);
                } else {
                    float2* pc = (float2*)&Cf[(size_t)r * N + cI];
                    if (MODE == 2) {
                        float2 cur = *pc;
                        v0 += cur.x; v1 += cur.y;
                    }
                    *pc = make_float2(v0, v1);
                }
            }
        }
    }
}

// ---------------- fp32 SGEMM (tiny classifier head) ----------------
template<int MODE>
__global__ void sgemm_kernel(const float* __restrict__ A, const float* __restrict__ B,
                             const float* __restrict__ bias, float* __restrict__ C,
                             int M, int N, int K, int lda) {
    __shared__ float As[8][128];
    __shared__ float Bs[8][128];
    int tid = threadIdx.x;
    int tx = tid & 15, ty = tid >> 4;
    int row0 = blockIdx.y * 128, col0 = blockIdx.x * 128;
    int arow = tid >> 1, acol = (tid & 1) * 4;
    int brow = tid >> 5, bcol = (tid & 31) * 4;

    float acc[8][8];
#pragma unroll
    for (int i = 0; i < 8; i++)
#pragma unroll
        for (int j = 0; j < 8; j++) acc[i][j] = 0.f;

    for (int k0 = 0; k0 < K; k0 += 8) {
        float4 av = make_float4(0.f, 0.f, 0.f, 0.f);
        if (row0 + arow < M)
            av = *(const float4*)(A + (size_t)(row0 + arow) * lda + k0 + acol);
        As[acol + 0][arow] = av.x;
        As[acol + 1][arow] = av.y;
        As[acol + 2][arow] = av.z;
        As[acol + 3][arow] = av.w;

        int bc = col0 + bcol;
        float4 bv = make_float4(0.f, 0.f, 0.f, 0.f);
        if (bc + 3 < N) {
            bv = *(const float4*)(B + (size_t)(k0 + brow) * N + bc);
        } else {
            float tmp[4] = {0.f, 0.f, 0.f, 0.f};
            for (int i = 0; i < 4; i++)
                if (bc + i < N) tmp[i] = B[(size_t)(k0 + brow) * N + bc + i];
            bv = make_float4(tmp[0], tmp[1], tmp[2], tmp[3]);
        }
        *(float4*)&Bs[brow][bcol] = bv;
        __syncthreads();

#pragma unroll
        for (int kk = 0; kk < 8; kk++) {
            float a[8], bb[8];
#pragma unroll
            for (int i = 0; i < 8; i++) a[i] = As[kk][ty * 8 + i];
#pragma unroll
            for (int j = 0; j < 8; j++) bb[j] = Bs[kk][tx * 8 + j];
#pragma unroll
            for (int i = 0; i < 8; i++)
#pragma unroll
                for (int j = 0; j < 8; j++) acc[i][j] = fmaf(a[i], bb[j], acc[i][j]);
        }
        __syncthreads();
    }

#pragma unroll
    for (int i = 0; i < 8; i++) {
        int r = row0 + ty * 8 + i;
        if (r >= M) continue;
#pragma unroll
        for (int j = 0; j < 8; j++) {
            int cI = col0 + tx * 8 + j;
            if (cI >= N) continue;
            float v = acc[i][j] + bias[cI];
            if (MODE == 1) v = 0.5f * v * (1.f + erff(v * 0.70710678118654752f));
            if (MODE == 2) v += C[(size_t)r * N + cI];
            C[(size_t)r * N + cI] = v;
        }
    }
}

// ---------------- LayerNorm over D=768 ----------------
template<int SPLIT>
__global__ void ln_kernel(const float* __restrict__ x, const float* __restrict__ g,
                          const float* __restrict__ be, float* __restrict__ o,
                          __half* __restrict__ oh) {
    int row = blockIdx.x, tid = threadIdx.x;
    const float* xr = x + (size_t)row * DIM;
    float v0 = xr[tid], v1 = xr[tid + 256], v2 = xr[tid + 512];
    __shared__ float red[32];
    int lane = tid & 31, w = tid >> 5;

    float s = v0 + v1 + v2;
#pragma unroll
    for (int off = 16; off; off >>= 1) s += __shfl_xor_sync(0xffffffffu, s, off);
    if (lane == 0) red[w] = s;
    __syncthreads();
    float tot = (lane < 8) ? red[lane] : 0.f;
#pragma unroll
    for (int off = 16; off; off >>= 1) tot += __shfl_xor_sync(0xffffffffu, tot, off);
    float mean = tot * (1.f / 768.f);

    float d0 = v0 - mean, d1 = v1 - mean, d2 = v2 - mean;
    float sq = d0 * d0 + d1 * d1 + d2 * d2;
#pragma unroll
    for (int off = 16; off; off >>= 1) sq += __shfl_xor_sync(0xffffffffu, sq, off);
    __syncthreads();
    if (lane == 0) red[w] = sq;
    __syncthreads();
    float tot2 = (lane < 8) ? red[lane] : 0.f;
#pragma unroll
    for (int off = 16; off; off >>= 1) tot2 += __shfl_xor_sync(0xffffffffu, tot2, off);
    float inv = rsqrtf(tot2 * (1.f / 768.f) + 1e-5f);

    float r0 = d0 * inv * g[tid]       + be[tid];
    float r1 = d1 * inv * g[tid + 256] + be[tid + 256];
    float r2 = d2 * inv * g[tid + 512] + be[tid + 512];
    if (SPLIT == 0) {
        float* orow = o + (size_t)row * DIM;
        orow[tid] = r0; orow[tid + 256] = r1; orow[tid + 512] = r2;
    } else {
        __half* orow = oh + (size_t)row * 2 * DIM;
        float vv[3] = {r0, r1, r2};
        int dd[3] = {tid, tid + 256, tid + 512};
#pragma unroll
        for (int j = 0; j < 3; j++) {
            __half h = __float2half_rn(vv[j]);
            orow[dd[j]]       = h;
            orow[DIM + dd[j]] = __float2half_rn(vv[j] - __half2float(h));
        }
    }
}

// ---------------- per-head QKV projection: 64x64 GEMMs ----------------
__global__ void qkv_kernel(const float* __restrict__ h,
                           const float* __restrict__ Wq, const float* __restrict__ bq,
                           const float* __restrict__ Wk, const float* __restrict__ bk,
                           const float* __restrict__ Wv, const float* __restrict__ bv,
                           float* __restrict__ q, float* __restrict__ k, float* __restrict__ v) {
    __shared__ float Xs[64 * 64];
    __shared__ float Ws[64 * 64];
    int hd = blockIdx.y;
    int r0 = blockIdx.x * 64;
    int tid = threadIdx.x;

    for (int i = tid; i < 4096; i += 256) {
        int rl = i >> 6, e = i & 63;
        int row = r0 + rl;
        Xs[i] = (row < RTOT) ? h[(size_t)row * DIM + hd * HDD + e] : 0.f;
    }

    int rg = tid >> 4, eg = tid & 15;
    const float* Wm[3] = {Wq + (size_t)hd * HDD * HDD, Wk + (size_t)hd * HDD * HDD, Wv + (size_t)hd * HDD * HDD};
    const float* bm[3] = {bq + hd * HDD, bk + hd * HDD, bv + hd * HDD};
    float* om[3] = {q, k, v};

    for (int m = 0; m < 3; m++) {
        __syncthreads();
        for (int i = tid; i < 4096; i += 256) Ws[i] = Wm[m][i];
        __syncthreads();
        float acc[4][4];
#pragma unroll
        for (int i = 0; i < 4; i++)
#pragma unroll
            for (int j = 0; j < 4; j++) acc[i][j] = 0.f;
#pragma unroll 16
        for (int kk = 0; kk < 64; kk++) {
            float a[4], bb[4];
#pragma unroll
            for (int i = 0; i < 4; i++) a[i] = Xs[(rg * 4 + i) * 64 + kk];
#pragma unroll
            for (int j = 0; j < 4; j++) bb[j] = Ws[kk * 64 + eg * 4 + j];
#pragma unroll
            for (int i = 0; i < 4; i++)
#pragma unroll
                for (int j = 0; j < 4; j++) acc[i][j] = fmaf(a[i], bb[j], acc[i][j]);
        }
        for (int i = 0; i < 4; i++) {
            int row = r0 + rg * 4 + i;
            if (row >= RTOT) continue;
            int b = row / SS, s = row % SS;
            float* op = om[m] + (((size_t)b * NHD + hd) * SS + s) * HDD + eg * 4;
            for (int j = 0; j < 4; j++) op[j] = acc[i][j] + bm[m][eg * 4 + j];
        }
    }
}

// ---------------- fused attention: scores+softmax+PV, x += out ----------------
#define KS_STRIDE 256
#define SC_STRIDE 208
#define ATTN_SMEM ((64*KS_STRIDE + SS*HDD + 64*32 + 32*SC_STRIDE) * 4)

__global__ void attn_kernel(const float* __restrict__ q, const float* __restrict__ k,
                            const float* __restrict__ v, float* __restrict__ x) {
    extern __shared__ float smf[];
    float* Ks  = smf;
    float* Vs  = Ks + 64 * KS_STRIDE;
    float* Qs  = Vs + SS * HDD;
    float* Ssc = Qs + 64 * 32;

    int bh = blockIdx.y;
    int b = bh / NHD, hh = bh % NHD;
    int qt = blockIdx.x;
    int tid = threadIdx.x;

    const float* kb = k + (size_t)bh * SS * HDD;
    const float* vb = v + (size_t)bh * SS * HDD;
    const float* qb = q + (size_t)bh * SS * HDD;

    for (int i = tid; i < 64 * KS_STRIDE; i += 256) Ks[i] = 0.f;
    __syncthreads();
    for (int i = tid; i < SS * HDD; i += 256) {
        int t = i >> 6, e = i & 63;
        Ks[e * KS_STRIDE + t] = kb[i];
        Vs[i] = vb[i];
    }
    for (int i = tid; i < 32 * 64; i += 256) {
        int e = i >> 5, qi = i & 31;
        int s = qt * 32 + qi;
        Qs[e * 32 + qi] = (s < SS) ? qb[(size_t)s * HDD + e] : 0.f;
    }
    __syncthreads();

    int qg = tid >> 5;
    int kg = tid & 31;
    {
        float acc[4][8];
#pragma unroll
        for (int i = 0; i < 4; i++)
#pragma unroll
            for (int j = 0; j < 8; j++) acc[i][j] = 0.f;
#pragma unroll 8
        for (int e = 0; e < 64; e++) {
            float4 a  = *(float4*)&Qs[e * 32 + qg * 4];
            float4 b0 = *(float4*)&Ks[e * KS_STRIDE + kg * 8];
            float4 b1 = *(float4*)&Ks[e * KS_STRIDE + kg * 8 + 4];
            float av[4] = {a.x, a.y, a.z, a.w};
            float bv8[8] = {b0.x, b0.y, b0.z, b0.w, b1.x, b1.y, b1.z, b1.w};
#pragma unroll
            for (int i = 0; i < 4; i++)
#pragma unroll
                for (int j = 0; j < 8; j++) acc[i][j] = fmaf(av[i], bv8[j], acc[i][j]);
        }
        for (int i = 0; i < 4; i++)
            for (int j = 0; j < 8; j++) {
                int t = kg * 8 + j;
                if (t < SS) Ssc[(qg * 4 + i) * SC_STRIDE + t] = acc[i][j] * 0.125f;
            }
    }
    __syncthreads();

    int lane = tid & 31, w = tid >> 5;
    for (int r = w * 4; r < w * 4 + 4; r++) {
        float mx = -1e30f;
        for (int t = lane; t < SS; t += 32) mx = fmaxf(mx, Ssc[r * SC_STRIDE + t]);
#pragma unroll
        for (int off = 16; off; off >>= 1) mx = fmaxf(mx, __shfl_xor_sync(0xffffffffu, mx, off));
        float sum = 0.f;
        for (int t = lane; t < SS; t += 32) {
            float p = expf(Ssc[r * SC_STRIDE + t] - mx);
            Ssc[r * SC_STRIDE + t] = p;
            sum += p;
        }
#pragma unroll
        for (int off = 16; off; off >>= 1) sum += __shfl_xor_sync(0xffffffffu, sum, off);
        float invs = 1.f / sum;
        for (int t = lane; t < SS; t += 32) Ssc[r * SC_STRIDE + t] *= invs;
    }
    __syncthreads();

    int qg2 = tid >> 4;
    int dg = tid & 15;
    float o0[4] = {0.f, 0.f, 0.f, 0.f}, o1[4] = {0.f, 0.f, 0.f, 0.f};
    int q0 = qg2 * 2;
    for (int t = 0; t < SS; t++) {
        float p0 = Ssc[q0 * SC_STRIDE + t];
        float p1 = Ssc[(q0 + 1) * SC_STRIDE + t];
        float4 vv = *(float4*)&Vs[t * 64 + dg * 4];
        o0[0] = fmaf(p0, vv.x, o0[0]); o0[1] = fmaf(p0, vv.y, o0[1]);
        o0[2] = fmaf(p0, vv.z, o0[2]); o0[3] = fmaf(p0, vv.w, o0[3]);
        o1[0] = fmaf(p1, vv.x, o1[0]); o1[1] = fmaf(p1, vv.y, o1[1]);
        o1[2] = fmaf(p1, vv.z, o1[2]); o1[3] = fmaf(p1, vv.w, o1[3]);
    }
    int s0 = qt * 32 + q0;
    if (s0 < SS) {
        float4* px = (float4*)&x[((size_t)(b * SS + s0)) * DIM + hh * HDD + dg * 4];
        float4 cur = *px;
        cur.x += o0[0]; cur.y += o0[1]; cur.z += o0[2]; cur.w += o0[3];
        *px = cur;
    }
    if (s0 + 1 < SS) {
        float4* px = (float4*)&x[((size_t)(b * SS + s0 + 1)) * DIM + hh * HDD + dg * 4];
        float4 cur = *px;
        cur.x += o1[0]; cur.y += o1[1]; cur.z += o1[2]; cur.w += o1[3];
        *px = cur;
    }
}

// ---------------- final softmax over 1000 classes ----------------
__global__ void softmax_out_kernel(const float* __restrict__ logits, float* __restrict__ out) {
    int b = blockIdx.x, tid = threadIdx.x;
    int lane = tid & 31, w = tid >> 5;
    __shared__ float red[32];
    const float* lr = logits + (size_t)b * NCLS;

    float mx = -1e30f;
    for (int i = tid; i < NCLS; i += 256) mx = fmaxf(mx, lr[i]);
#pragma unroll
    for (int off = 16; off; off >>= 1) mx = fmaxf(mx, __shfl_xor_sync(0xffffffffu, mx, off));
    if (lane == 0) red[w] = mx;
    __syncthreads();
    float gm = (lane < 8) ? red[lane] : -1e30f;
#pragma unroll
    for (int off = 16; off; off >>= 1) gm = fmaxf(gm, __shfl_xor_sync(0xffffffffu, gm, off));

    float sum = 0.f;
    for (int i = tid; i < NCLS; i += 256) sum += expf(lr[i] - gm);
#pragma unroll
    for (int off = 16; off; off >>= 1) sum += __shfl_xor_sync(0xffffffffu, sum, off);
    __syncthreads();
    if (lane == 0) red[w] = sum;
    __syncthreads();
    float gs = (lane < 8) ? red[lane] : 0.f;
#pragma unroll
    for (int off = 16; off; off >>= 1) gs += __shfl_xor_sync(0xffffffffu, gs, off);
    float invs = 1.f / gs;

    for (int i = tid; i < NCLS; i += 256) out[(size_t)b * NCLS + i] = expf(lr[i] - gm) * invs;
}

// ---------------- launch ----------------
extern "C" void kernel_launch(void* const* d_in, const int* in_sizes, int n_in,
                              void* d_out, int out_size) {
    const float* images = (const float*)d_in[0];
    const float* Wp  = (const float*)d_in[1];
    const float* bp  = (const float*)d_in[2];
    const float* cls = (const float*)d_in[3];
    const float* pos = (const float*)d_in[4];
    const float* ln1_g = (const float*)d_in[5];
    const float* ln1_b = (const float*)d_in[6];
    const float* Wq = (const float*)d_in[7];
    const float* bq = (const float*)d_in[8];
    const float* Wk = (const float*)d_in[9];
    const float* bk = (const float*)d_in[10];
    const float* Wv = (const float*)d_in[11];
    const float* bv = (const float*)d_in[12];
    const float* ln2_g = (const float*)d_in[13];
    const float* ln2_b = (const float*)d_in[14];
    const float* W1 = (const float*)d_in[15];
    const float* b1 = (const float*)d_in[16];
    const float* W2 = (const float*)d_in[17];
    const float* b2 = (const float*)d_in[18];
    const float* Wh = (const float*)d_in[19];
    const float* bh = (const float*)d_in[20];
    float* out = (float*)d_out;

    float *pP, *pX, *pH, *pQ, *pK, *pV, *pL;
    __half *pAS, *pBS, *pWS;
    cudaGetSymbolAddress((void**)&pP, g_patches);
    cudaGetSymbolAddress((void**)&pX, g_x);
    cudaGetSymbolAddress((void**)&pH, g_h);
    cudaGetSymbolAddress((void**)&pQ, g_q);
    cudaGetSymbolAddress((void**)&pK, g_k);
    cudaGetSymbolAddress((void**)&pV, g_v);
    cudaGetSymbolAddress((void**)&pL, g_logits);
    cudaGetSymbolAddress((void**)&pAS, g_as);
    cudaGetSymbolAddress((void**)&pBS, g_bs);
    cudaGetSymbolAddress((void**)&pWS, g_ws);

    cudaFuncSetAttribute(attn_kernel, cudaFuncAttributeMaxDynamicSharedMemorySize, ATTN_SMEM);
    cudaFuncSetAttribute(hgemm_kernel<0>, cudaFuncAttributeMaxDynamicSharedMemorySize, GEMM_SMEM);
    cudaFuncSetAttribute(hgemm_kernel<1>, cudaFuncAttributeMaxDynamicSharedMemorySize, GEMM_SMEM);
    cudaFuncSetAttribute(hgemm_kernel<2>, cudaFuncAttributeMaxDynamicSharedMemorySize, GEMM_SMEM);

    dim3 wtThreads(32, 8);

    // patch embedding
    patchify_kernel<<<(PTOT * DIM + 255) / 256, 256>>>(images, pP);
    splitA_kernel<<<((PTOT * DIM / 4) + 255) / 256, 256>>>(pP, pBS, PTOT, DIM);
    splitWT_kernel<<<dim3(DIM / 32, DIM / 32), wtThreads>>>(Wp, pWS, DIM, DIM);
    hgemm_kernel<0><<<dim3(12, 49), 256, GEMM_SMEM>>>(pBS, pWS, bp, pH, nullptr, PTOT, DIM, DIM);
    assemble_kernel<<<(RTOT * DIM + 255) / 256, 256>>>(pH, cls, pos, pX);

    for (int l = 0; l < LL; l++) {
        ln_kernel<0><<<RTOT, 256>>>(pX, ln1_g + l * DIM, ln1_b + l * DIM, pH, nullptr);
        qkv_kernel<<<dim3((RTOT + 63) / 64, NHD), 256>>>(
            pH,
            Wq + (size_t)l * NHD * HDD * HDD, bq + (size_t)l * NHD * HDD,
            Wk + (size_t)l * NHD * HDD * HDD, bk + (size_t)l * NHD * HDD,
            Wv + (size_t)l * NHD * HDD * HDD, bv + (size_t)l * NHD * HDD,
            pQ, pK, pV);
        attn_kernel<<<dim3((SS + 31) / 32, BB * NHD), 256, ATTN_SMEM>>>(pQ, pK, pV, pX);
        // ln2 writes split fp16 directly (MLP1 A input)
        ln_kernel<1><<<RTOT, 256>>>(pX, ln2_g + l * DIM, ln2_b + l * DIM, nullptr, pBS);

        // MLP1: gelu epilogue writes split fp16 directly (MLP2 A input)
        splitWT_kernel<<<dim3(MLPD / 32, DIM / 32), wtThreads>>>(W1 + (size_t)l * DIM * MLPD, pWS, DIM, MLPD);
        hgemm_kernel<1><<<dim3(48, 50), 256, GEMM_SMEM>>>(pBS, pWS, b1 + (size_t)l * MLPD,
                                                          nullptr, pAS, RTOT, MLPD, DIM);
        // MLP2: + residual into pX
        splitWT_kernel<<<dim3(DIM / 32, MLPD / 32), wtThreads>>>(W2 + (size_t)l * MLPD * DIM, pWS, MLPD, DIM);
        hgemm_kernel<2><<<dim3(12, 50), 256, GEMM_SMEM>>>(pAS, pWS, b2 + (size_t)l * DIM,
                                                          pX, nullptr, RTOT, DIM, MLPD);
    }

    // classifier head on CLS token (row stride = S*D)
    sgemm_kernel<0><<<dim3(8, 1), 256>>>(pX, Wh, bh, pL, BB, NCLS, DIM, SS * DIM);
    softmax_out_kernel<<<BB, 256>>>(pL, out);
}

// round 10
// speedup vs baseline: 1.1218x; 1.1218x over previous
#include <cuda_runtime.h>
#include <cuda_fp16.h>
#include <math.h>
#include <cstdint>

#define BB 32
#define CC 3
#define IMGSZ 224
#define NP 14
#define PS 16
#define DIM 768
#define NHD 12
#define HDD 64
#define LL 12
#define NCLS 1000
#define SS 197
#define MLPD 3072
#define RTOT (BB*SS)      /* 6304 rows */
#define PTOT (BB*NP*NP)   /* 6272 patch rows */

// ---------------- scratch (device globals; no allocations) ----------------
__device__ float g_patches[PTOT*DIM];
__device__ float g_x[RTOT*DIM];
__device__ float g_h[RTOT*DIM];
__device__ float g_q[RTOT*DIM];
__device__ float g_k[RTOT*DIM];
__device__ float g_v[RTOT*DIM];
__device__ float g_logits[BB*NCLS];
__device__ __half g_as[(size_t)RTOT*2*MLPD];     // split MLP hidden [M, 2*MLPD]
__device__ __half g_bs[(size_t)RTOT*2*DIM];      // split D-wide activations [M, 2*DIM]
__device__ __half g_ws[(size_t)MLPD*2*DIM];      // split transposed weights [N, 2K] max

#define CP_ASYNC16(dst, src) \
    asm volatile("cp.async.cg.shared.global [%0], [%1], 16;" :: "r"(dst), "l"(src) : "memory")

__device__ __forceinline__ uint32_t smem_u32(const void* p) {
    uint32_t a;
    asm("{ .reg .u64 t; cvta.to.shared.u64 t, %1; cvt.u32.u64 %0, t; }" : "=r"(a) : "l"(p));
    return a;
}

#define MMA16816(c, a, b)                                                        \
    asm volatile("mma.sync.aligned.m16n8k16.row.col.f32.f16.f16.f32 "            \
                 "{%0,%1,%2,%3},{%4,%5,%6,%7},{%8,%9},{%0,%1,%2,%3};"            \
                 : "+f"(c[0]), "+f"(c[1]), "+f"(c[2]), "+f"(c[3])                \
                 : "r"(a[0]), "r"(a[1]), "r"(a[2]), "r"(a[3]), "r"(b[0]), "r"(b[1]));

// ---------------- patchify: (B,C,H,W) -> (B,196,768) ----------------
__global__ void patchify_kernel(const float* __restrict__ img, float* __restrict__ out) {
    int idx = blockIdx.x * blockDim.x + threadIdx.x;
    if (idx >= PTOT * DIM) return;
    int f = idx % DIM;
    int t = (idx / DIM) % (NP * NP);
    int b = idx / (DIM * NP * NP);
    int c  = f >> 8;
    int iy = (f >> 4) & 15;
    int ix = f & 15;
    int py = t / NP, px = t % NP;
    out[idx] = img[(((size_t)b * CC + c) * IMGSZ + py * PS + iy) * IMGSZ + px * PS + ix];
}

// ---------------- assemble x = concat(cls, tokens) + pos ----------------
__global__ void assemble_kernel(const float* __restrict__ tok, const float* __restrict__ cls,
                                const float* __restrict__ pos, float* __restrict__ x) {
    int idx = blockIdx.x * blockDim.x + threadIdx.x;
    if (idx >= RTOT * DIM) return;
    int d = idx % DIM;
    int s = (idx / DIM) % SS;
    int b = idx / (DIM * SS);
    float v = (s == 0) ? cls[d] : tok[((size_t)b * (NP * NP) + (s - 1)) * DIM + d];
    x[idx] = v + pos[s * DIM + d];
}

// ---------------- fp16 split conversions ----------------
__global__ void splitA_kernel(const float* __restrict__ in, __half* __restrict__ out,
                              int M, int K) {
    int i = blockIdx.x * 256 + threadIdx.x;
    int total = (M * K) >> 2;
    if (i >= total) return;
    int e0 = i << 2;
    int m = e0 / K, k = e0 % K;
    float4 v = *(const float4*)(in + e0);
    __half h[4], l[4];
    float vv[4] = {v.x, v.y, v.z, v.w};
#pragma unroll
    for (int j = 0; j < 4; j++) {
        h[j] = __float2half_rn(vv[j]);
        l[j] = __float2half_rn(vv[j] - __half2float(h[j]));
    }
    __half* oh = out + (size_t)m * 2 * K + k;
    *(uint2*)oh         = *(uint2*)h;
    *(uint2*)(oh + K)   = *(uint2*)l;
}

// W: fp32 [K,N] -> fp16 [N,2K] (transpose + split)
__global__ void splitWT_kernel(const float* __restrict__ W, __half* __restrict__ out,
                               int K, int N) {
    __shared__ float t[32][33];
    int n0 = blockIdx.x * 32, k0 = blockIdx.y * 32;
    int tx = threadIdx.x, ty = threadIdx.y;   // 32 x 8
#pragma unroll
    for (int j = 0; j < 32; j += 8)
        t[ty + j][tx] = W[(size_t)(k0 + ty + j) * N + n0 + tx];
    __syncthreads();
#pragma unroll
    for (int j = 0; j < 32; j += 8) {
        float v = t[tx][ty + j];
        __half h = __float2half_rn(v);
        __half l = __float2half_rn(v - __half2float(h));
        size_t base = (size_t)(n0 + ty + j) * 2 * K;
        out[base + k0 + tx]     = h;
        out[base + K + k0 + tx] = l;
    }
}

// ================= fp16 mma.sync 3-pass split GEMM, 2-stage, 2 CTAs/SM (R8 best) =================
#define TSTRIDE 80                 /* bytes per smem row */
#define TILE_B (128 * TSTRIDE)     /* 10240 B per tile */
#define STAGE_B (4 * TILE_B)       /* Ah, Al, Bh, Bl : 40960 B */
#define NSTAGE 2
#define GEMM_SMEM (NSTAGE * STAGE_B)   /* 81920 B -> 2 CTAs/SM */

template<int MODE>
__global__ __launch_bounds__(256, 2)
void hgemm_kernel(const __half* __restrict__ A, const __half* __restrict__ Bw,
                  const float* __restrict__ bias, float* __restrict__ Cf,
                  __half* __restrict__ Ch, int M, int N, int K) {
    extern __shared__ char smc[];
    uint32_t smb = smem_u32(smc);

    int tid = threadIdx.x, lane = tid & 31, warp = tid >> 5;
    int wm = warp & 1, wn = warp >> 1;          // 2 x 4 warps; warp tile 64 x 32
    int g = lane >> 2, q = lane & 3;
    int row0 = blockIdx.y * 128, col0 = blockIdx.x * 128;
    int K2 = 2 * K;

    float c[4][4][4];
#pragma unroll
    for (int mi = 0; mi < 4; mi++)
#pragma unroll
        for (int ni = 0; ni < 4; ni++)
#pragma unroll
            for (int j = 0; j < 4; j++) c[mi][ni][j] = 0.f;

    int lr = tid >> 1;
    int sg0 = (tid & 1) * 2;
    int garow = row0 + lr; if (garow >= M) garow = M - 1;
    const __half* aRow = A + (size_t)garow * K2;
    const __half* bRow = Bw + (size_t)(col0 + lr) * K2;
    uint32_t dOff = lr * TSTRIDE;

    auto load_chunk = [&](int ck) {
        uint32_t base = smb + (uint32_t)(ck & 1) * STAGE_B;
        int k0 = ck * 32;
#pragma unroll
        for (int s = 0; s < 2; s++) {
            int seg = sg0 + s;
            uint32_t d = dOff + seg * 16;
            int srcO = k0 + seg * 8;
            CP_ASYNC16(base + d,              aRow + srcO);          // Ah
            CP_ASYNC16(base + TILE_B + d,     aRow + K + srcO);      // Al
            CP_ASYNC16(base + 2 * TILE_B + d, bRow + srcO);          // Bh
            CP_ASYNC16(base + 3 * TILE_B + d, bRow + K + srcO);      // Bl
        }
        asm volatile("cp.async.commit_group;" ::: "memory");
    };

    int nc = K >> 5;
    load_chunk(0);

    for (int ck = 0; ck < nc; ck++) {
        asm volatile("cp.async.wait_group 0;" ::: "memory");   // chunk ck landed
        __syncthreads();                                       // all warps done with old buffer
        if (ck + 1 < nc) load_chunk(ck + 1);                   // overlaps compute of ck

        const char* bufA = smc + (size_t)(ck & 1) * STAGE_B;
#pragma unroll
        for (int kk = 0; kk < 2; kk++) {
            uint32_t ah[4][4], al[4][4], bh[4][2], bl[4][2];
#pragma unroll
            for (int mi = 0; mi < 4; mi++) {
                uint32_t o = (uint32_t)(wm * 64 + mi * 16 + g) * TSTRIDE + kk * 32 + q * 4;
                ah[mi][0] = *(const uint32_t*)(bufA + o);
                ah[mi][1] = *(const uint32_t*)(bufA + o + 8 * TSTRIDE);
                ah[mi][2] = *(const uint32_t*)(bufA + o + 16);
                ah[mi][3] = *(const uint32_t*)(bufA + o + 8 * TSTRIDE + 16);
                al[mi][0] = *(const uint32_t*)(bufA + TILE_B + o);
                al[mi][1] = *(const uint32_t*)(bufA + TILE_B + o + 8 * TSTRIDE);
                al[mi][2] = *(const uint32_t*)(bufA + TILE_B + o + 16);
                al[mi][3] = *(const uint32_t*)(bufA + TILE_B + o + 8 * TSTRIDE + 16);
            }
#pragma unroll
            for (int ni = 0; ni < 4; ni++) {
                uint32_t o = (uint32_t)(wn * 32 + ni * 8 + g) * TSTRIDE + kk * 32 + q * 4;
                bh[ni][0] = *(const uint32_t*)(bufA + 2 * TILE_B + o);
                bh[ni][1] = *(const uint32_t*)(bufA + 2 * TILE_B + o + 16);
                bl[ni][0] = *(const uint32_t*)(bufA + 3 * TILE_B + o);
                bl[ni][1] = *(const uint32_t*)(bufA + 3 * TILE_B + o + 16);
            }
#pragma unroll
            for (int mi = 0; mi < 4; mi++)
#pragma unroll
                for (int ni = 0; ni < 4; ni++) {
                    MMA16816(c[mi][ni], ah[mi], bh[ni]);
                    MMA16816(c[mi][ni], ah[mi], bl[ni]);
                    MMA16816(c[mi][ni], al[mi], bh[ni]);
                }
        }
    }

    // ---- epilogue ----
#pragma unroll
    for (int mi = 0; mi < 4; mi++) {
        int r0 = row0 + wm * 64 + mi * 16 + g;
        int r1 = r0 + 8;
#pragma unroll
        for (int ni = 0; ni < 4; ni++) {
            int cI = col0 + wn * 32 + ni * 8 + 2 * q;
            float2 bv = *(const float2*)&bias[cI];
#pragma unroll
            for (int h = 0; h < 2; h++) {
                int r = h ? r1 : r0;
                if (r >= M) continue;
                float v0 = c[mi][ni][h * 2 + 0] + bv.x;
                float v1 = c[mi][ni][h * 2 + 1] + bv.y;
                if (MODE == 1) {
                    v0 = 0.5f * v0 * (1.f + erff(v0 * 0.70710678118654752f));
                    v1 = 0.5f * v1 * (1.f + erff(v1 * 0.70710678118654752f));
                    __half h0 = __float2half_rn(v0);
                    __half h1 = __float2half_rn(v1);
                    __half l0 = __float2half_rn(v0 - __half2float(h0));
                    __half l1 = __float2half_rn(v1 - __half2float(h1));
                    size_t rb = (size_t)r * 2 * N;
                    *(__half2*)&Ch[rb + cI]     = __halves2half2(h0, h1);
                    *(__half2*)&Ch[rb + N + cI] = __halves2half2(l0, l1);
                } else {
                    float2* pc = (float2*)&Cf[(size_t)r * N + cI];
                    if (MODE == 2) {
                        float2 cur = *pc;
                        v0 += cur.x; v1 += cur.y;
                    }
                    *pc = make_float2(v0, v1);
                }
            }
        }
    }
}

// ---------------- fp32 SGEMM (tiny classifier head) ----------------
template<int MODE>
__global__ void sgemm_kernel(const float* __restrict__ A, const float* __restrict__ B,
                             const float* __restrict__ bias, float* __restrict__ C,
                             int M, int N, int K, int lda) {
    __shared__ float As[8][128];
    __shared__ float Bs[8][128];
    int tid = threadIdx.x;
    int tx = tid & 15, ty = tid >> 4;
    int row0 = blockIdx.y * 128, col0 = blockIdx.x * 128;
    int arow = tid >> 1, acol = (tid & 1) * 4;
    int brow = tid >> 5, bcol = (tid & 31) * 4;

    float acc[8][8];
#pragma unroll
    for (int i = 0; i < 8; i++)
#pragma unroll
        for (int j = 0; j < 8; j++) acc[i][j] = 0.f;

    for (int k0 = 0; k0 < K; k0 += 8) {
        float4 av = make_float4(0.f, 0.f, 0.f, 0.f);
        if (row0 + arow < M)
            av = *(const float4*)(A + (size_t)(row0 + arow) * lda + k0 + acol);
        As[acol + 0][arow] = av.x;
        As[acol + 1][arow] = av.y;
        As[acol + 2][arow] = av.z;
        As[acol + 3][arow] = av.w;

        int bc = col0 + bcol;
        float4 bv = make_float4(0.f, 0.f, 0.f, 0.f);
        if (bc + 3 < N) {
            bv = *(const float4*)(B + (size_t)(k0 + brow) * N + bc);
        } else {
            float tmp[4] = {0.f, 0.f, 0.f, 0.f};
            for (int i = 0; i < 4; i++)
                if (bc + i < N) tmp[i] = B[(size_t)(k0 + brow) * N + bc + i];
            bv = make_float4(tmp[0], tmp[1], tmp[2], tmp[3]);
        }
        *(float4*)&Bs[brow][bcol] = bv;
        __syncthreads();

#pragma unroll
        for (int kk = 0; kk < 8; kk++) {
            float a[8], bb[8];
#pragma unroll
            for (int i = 0; i < 8; i++) a[i] = As[kk][ty * 8 + i];
#pragma unroll
            for (int j = 0; j < 8; j++) bb[j] = Bs[kk][tx * 8 + j];
#pragma unroll
            for (int i = 0; i < 8; i++)
#pragma unroll
                for (int j = 0; j < 8; j++) acc[i][j] = fmaf(a[i], bb[j], acc[i][j]);
        }
        __syncthreads();
    }

#pragma unroll
    for (int i = 0; i < 8; i++) {
        int r = row0 + ty * 8 + i;
        if (r >= M) continue;
#pragma unroll
        for (int j = 0; j < 8; j++) {
            int cI = col0 + tx * 8 + j;
            if (cI >= N) continue;
            float v = acc[i][j] + bias[cI];
            if (MODE == 1) v = 0.5f * v * (1.f + erff(v * 0.70710678118654752f));
            if (MODE == 2) v += C[(size_t)r * N + cI];
            C[(size_t)r * N + cI] = v;
        }
    }
}

// ---------------- LayerNorm over D=768 ----------------
template<int SPLIT>
__global__ void ln_kernel(const float* __restrict__ x, const float* __restrict__ g,
                          const float* __restrict__ be, float* __restrict__ o,
                          __half* __restrict__ oh) {
    int row = blockIdx.x, tid = threadIdx.x;
    const float* xr = x + (size_t)row * DIM;
    float v0 = xr[tid], v1 = xr[tid + 256], v2 = xr[tid + 512];
    __shared__ float red[32];
    int lane = tid & 31, w = tid >> 5;

    float s = v0 + v1 + v2;
#pragma unroll
    for (int off = 16; off; off >>= 1) s += __shfl_xor_sync(0xffffffffu, s, off);
    if (lane == 0) red[w] = s;
    __syncthreads();
    float tot = (lane < 8) ? red[lane] : 0.f;
#pragma unroll
    for (int off = 16; off; off >>= 1) tot += __shfl_xor_sync(0xffffffffu, tot, off);
    float mean = tot * (1.f / 768.f);

    float d0 = v0 - mean, d1 = v1 - mean, d2 = v2 - mean;
    float sq = d0 * d0 + d1 * d1 + d2 * d2;
#pragma unroll
    for (int off = 16; off; off >>= 1) sq += __shfl_xor_sync(0xffffffffu, sq, off);
    __syncthreads();
    if (lane == 0) red[w] = sq;
    __syncthreads();
    float tot2 = (lane < 8) ? red[lane] : 0.f;
#pragma unroll
    for (int off = 16; off; off >>= 1) tot2 += __shfl_xor_sync(0xffffffffu, tot2, off);
    float inv = rsqrtf(tot2 * (1.f / 768.f) + 1e-5f);

    float r0 = d0 * inv * g[tid]       + be[tid];
    float r1 = d1 * inv * g[tid + 256] + be[tid + 256];
    float r2 = d2 * inv * g[tid + 512] + be[tid + 512];
    if (SPLIT == 0) {
        float* orow = o + (size_t)row * DIM;
        orow[tid] = r0; orow[tid + 256] = r1; orow[tid + 512] = r2;
    } else {
        __half* orow = oh + (size_t)row * 2 * DIM;
        float vv[3] = {r0, r1, r2};
        int dd[3] = {tid, tid + 256, tid + 512};
#pragma unroll
        for (int j = 0; j < 3; j++) {
            __half h = __float2half_rn(vv[j]);
            orow[dd[j]]       = h;
            orow[DIM + dd[j]] = __float2half_rn(vv[j] - __half2float(h));
        }
    }
}

// ---------------- per-head QKV projection: 64x64 GEMMs ----------------
__global__ void qkv_kernel(const float* __restrict__ h,
                           const float* __restrict__ Wq, const float* __restrict__ bq,
                           const float* __restrict__ Wk, const float* __restrict__ bk,
                           const float* __restrict__ Wv, const float* __restrict__ bv,
                           float* __restrict__ q, float* __restrict__ k, float* __restrict__ v) {
    __shared__ float Xs[64 * 64];
    __shared__ float Ws[64 * 64];
    int hd = blockIdx.y;
    int r0 = blockIdx.x * 64;
    int tid = threadIdx.x;

    for (int i = tid; i < 4096; i += 256) {
        int rl = i >> 6, e = i & 63;
        int row = r0 + rl;
        Xs[i] = (row < RTOT) ? h[(size_t)row * DIM + hd * HDD + e] : 0.f;
    }

    int rg = tid >> 4, eg = tid & 15;
    const float* Wm[3] = {Wq + (size_t)hd * HDD * HDD, Wk + (size_t)hd * HDD * HDD, Wv + (size_t)hd * HDD * HDD};
    const float* bm[3] = {bq + hd * HDD, bk + hd * HDD, bv + hd * HDD};
    float* om[3] = {q, k, v};

    for (int m = 0; m < 3; m++) {
        __syncthreads();
        for (int i = tid; i < 4096; i += 256) Ws[i] = Wm[m][i];
        __syncthreads();
        float acc[4][4];
#pragma unroll
        for (int i = 0; i < 4; i++)
#pragma unroll
            for (int j = 0; j < 4; j++) acc[i][j] = 0.f;
#pragma unroll 16
        for (int kk = 0; kk < 64; kk++) {
            float a[4], bb[4];
#pragma unroll
            for (int i = 0; i < 4; i++) a[i] = Xs[(rg * 4 + i) * 64 + kk];
#pragma unroll
            for (int j = 0; j < 4; j++) bb[j] = Ws[kk * 64 + eg * 4 + j];
#pragma unroll
            for (int i = 0; i < 4; i++)
#pragma unroll
                for (int j = 0; j < 4; j++) acc[i][j] = fmaf(a[i], bb[j], acc[i][j]);
        }
        for (int i = 0; i < 4; i++) {
            int row = r0 + rg * 4 + i;
            if (row >= RTOT) continue;
            int b = row / SS, s = row % SS;
            float* op = om[m] + (((size_t)b * NHD + hd) * SS + s) * HDD + eg * 4;
            for (int j = 0; j < 4; j++) op[j] = acc[i][j] + bm[m][eg * 4 + j];
        }
    }
}

// ---------------- fused attention: one CTA per (b,h); K/V loaded ONCE ----------------
#define KS_STRIDE 208
#define SC_STRIDE 208
#define ATTN_SMEM ((64*KS_STRIDE + SS*HDD + 64*32 + 32*SC_STRIDE) * 4)

__global__ void attn_kernel(const float* __restrict__ q, const float* __restrict__ k,
                            const float* __restrict__ v, float* __restrict__ x) {
    extern __shared__ float smf[];
    float* Ks  = smf;                       // [64][208] e-major, zero-padded
    float* Vs  = Ks + 64 * KS_STRIDE;       // [197][64]
    float* Qs  = Vs + SS * HDD;             // [64][32] e-major
    float* Ssc = Qs + 64 * 32;              // [32][208]

    int bh = blockIdx.x;
    int b = bh / NHD, hh = bh % NHD;
    int tid = threadIdx.x;
    int lane = tid & 31, w = tid >> 5;

    const float* kb = k + (size_t)bh * SS * HDD;
    const float* vb = v + (size_t)bh * SS * HDD;
    const float* qb = q + (size_t)bh * SS * HDD;

    // zero K padding once, then load K (e-major) and V
    for (int i = tid; i < 64 * KS_STRIDE; i += 256) Ks[i] = 0.f;
    __syncthreads();
    for (int i = tid; i < SS * HDD; i += 256) {
        int t = i >> 6, e = i & 63;
        Ks[e * KS_STRIDE + t] = kb[i];
        Vs[i] = vb[i];
    }
    __syncthreads();

    for (int qt = 0; qt < (SS + 31) / 32; qt++) {
        // load 32 queries (e-major)
        for (int i = tid; i < 32 * 64; i += 256) {
            int e = i >> 5, qi = i & 31;
            int s = qt * 32 + qi;
            Qs[e * 32 + qi] = (s < SS) ? qb[(size_t)s * HDD + e] : 0.f;
        }
        __syncthreads();

        // QK^T: warp qg -> 4 queries; lane kg -> 8 keys
        int qg = w;          // 0..7
        int kg = lane;       // keys kg*8..kg*8+7
        {
            float acc[4][8];
#pragma unroll
            for (int i = 0; i < 4; i++)
#pragma unroll
                for (int j = 0; j < 8; j++) acc[i][j] = 0.f;
#pragma unroll 8
            for (int e = 0; e < 64; e++) {
                float4 a  = *(float4*)&Qs[e * 32 + qg * 4];
                float4 b0 = *(float4*)&Ks[e * KS_STRIDE + kg * 8];
                float4 b1 = *(float4*)&Ks[e * KS_STRIDE + kg * 8 + 4];
                float av[4] = {a.x, a.y, a.z, a.w};
                float bv8[8] = {b0.x, b0.y, b0.z, b0.w, b1.x, b1.y, b1.z, b1.w};
#pragma unroll
                for (int i = 0; i < 4; i++)
#pragma unroll
                    for (int j = 0; j < 8; j++) acc[i][j] = fmaf(av[i], bv8[j], acc[i][j]);
            }
            for (int i = 0; i < 4; i++)
                for (int j = 0; j < 8; j++) {
                    int t = kg * 8 + j;
                    if (t < SS) Ssc[(qg * 4 + i) * SC_STRIDE + t] = acc[i][j] * 0.125f;
                }
        }
        __syncthreads();

        // softmax: warp w -> rows w*4 .. w*4+3
        for (int r = w * 4; r < w * 4 + 4; r++) {
            float mx = -1e30f;
            for (int t = lane; t < SS; t += 32) mx = fmaxf(mx, Ssc[r * SC_STRIDE + t]);
#pragma unroll
            for (int off = 16; off; off >>= 1) mx = fmaxf(mx, __shfl_xor_sync(0xffffffffu, mx, off));
            float sum = 0.f;
            for (int t = lane; t < SS; t += 32) {
                float p = expf(Ssc[r * SC_STRIDE + t] - mx);
                Ssc[r * SC_STRIDE + t] = p;
                sum += p;
            }
#pragma unroll
            for (int off = 16; off; off >>= 1) sum += __shfl_xor_sync(0xffffffffu, sum, off);
            float invs = 1.f / sum;
            for (int t = lane; t < SS; t += 32) Ssc[r * SC_STRIDE + t] *= invs;
        }
        __syncthreads();

        // PV: thread -> 2 queries x 4 dims
        int qg2 = tid >> 4;       // queries qg2*2, qg2*2+1
        int dg = tid & 15;        // dims dg*4..dg*4+3
        float o0[4] = {0.f, 0.f, 0.f, 0.f}, o1[4] = {0.f, 0.f, 0.f, 0.f};
        int q0 = qg2 * 2;
        for (int t = 0; t < SS; t++) {
            float p0 = Ssc[q0 * SC_STRIDE + t];
            float p1 = Ssc[(q0 + 1) * SC_STRIDE + t];
            float4 vv = *(float4*)&Vs[t * 64 + dg * 4];
            o0[0] = fmaf(p0, vv.x, o0[0]); o0[1] = fmaf(p0, vv.y, o0[1]);
            o0[2] = fmaf(p0, vv.z, o0[2]); o0[3] = fmaf(p0, vv.w, o0[3]);
            o1[0] = fmaf(p1, vv.x, o1[0]); o1[1] = fmaf(p1, vv.y, o1[1]);
            o1[2] = fmaf(p1, vv.z, o1[2]); o1[3] = fmaf(p1, vv.w, o1[3]);
        }
        int s0 = qt * 32 + q0;
        if (s0 < SS) {
            float4* px = (float4*)&x[((size_t)(b * SS + s0)) * DIM + hh * HDD + dg * 4];
            float4 cur = *px;
            cur.x += o0[0]; cur.y += o0[1]; cur.z += o0[2]; cur.w += o0[3];
            *px = cur;
        }
        if (s0 + 1 < SS) {
            float4* px = (float4*)&x[((size_t)(b * SS + s0 + 1)) * DIM + hh * HDD + dg * 4];
            float4 cur = *px;
            cur.x += o1[0]; cur.y += o1[1]; cur.z += o1[2]; cur.w += o1[3];
            *px = cur;
        }
        __syncthreads();   // protect Qs/Ssc reuse next iteration
    }
}

// ---------------- final softmax over 1000 classes ----------------
__global__ void softmax_out_kernel(const float* __restrict__ logits, float* __restrict__ out) {
    int b = blockIdx.x, tid = threadIdx.x;
    int lane = tid & 31, w = tid >> 5;
    __shared__ float red[32];
    const float* lr = logits + (size_t)b * NCLS;

    float mx = -1e30f;
    for (int i = tid; i < NCLS; i += 256) mx = fmaxf(mx, lr[i]);
#pragma unroll
    for (int off = 16; off; off >>= 1) mx = fmaxf(mx, __shfl_xor_sync(0xffffffffu, mx, off));
    if (lane == 0) red[w] = mx;
    __syncthreads();
    float gm = (lane < 8) ? red[lane] : -1e30f;
#pragma unroll
    for (int off = 16; off; off >>= 1) gm = fmaxf(gm, __shfl_xor_sync(0xffffffffu, gm, off));

    float sum = 0.f;
    for (int i = tid; i < NCLS; i += 256) sum += expf(lr[i] - gm);
#pragma unroll
    for (int off = 16; off; off >>= 1) sum += __shfl_xor_sync(0xffffffffu, sum, off);
    __syncthreads();
    if (lane == 0) red[w] = sum;
    __syncthreads();
    float gs = (lane < 8) ? red[lane] : 0.f;
#pragma unroll
    for (int off = 16; off; off >>= 1) gs += __shfl_xor_sync(0xffffffffu, gs, off);
    float invs = 1.f / gs;

    for (int i = tid; i < NCLS; i += 256) out[(size_t)b * NCLS + i] = expf(lr[i] - gm) * invs;
}

// ---------------- launch ----------------
extern "C" void kernel_launch(void* const* d_in, const int* in_sizes, int n_in,
                              void* d_out, int out_size) {
    const float* images = (const float*)d_in[0];
    const float* Wp  = (const float*)d_in[1];
    const float* bp  = (const float*)d_in[2];
    const float* cls = (const float*)d_in[3];
    const float* pos = (const float*)d_in[4];
    const float* ln1_g = (const float*)d_in[5];
    const float* ln1_b = (const float*)d_in[6];
    const float* Wq = (const float*)d_in[7];
    const float* bq = (const float*)d_in[8];
    const float* Wk = (const float*)d_in[9];
    const float* bk = (const float*)d_in[10];
    const float* Wv = (const float*)d_in[11];
    const float* bv = (const float*)d_in[12];
    const float* ln2_g = (const float*)d_in[13];
    const float* ln2_b = (const float*)d_in[14];
    const float* W1 = (const float*)d_in[15];
    const float* b1 = (const float*)d_in[16];
    const float* W2 = (const float*)d_in[17];
    const float* b2 = (const float*)d_in[18];
    const float* Wh = (const float*)d_in[19];
    const float* bh = (const float*)d_in[20];
    float* out = (float*)d_out;

    float *pP, *pX, *pH, *pQ, *pK, *pV, *pL;
    __half *pAS, *pBS, *pWS;
    cudaGetSymbolAddress((void**)&pP, g_patches);
    cudaGetSymbolAddress((void**)&pX, g_x);
    cudaGetSymbolAddress((void**)&pH, g_h);
    cudaGetSymbolAddress((void**)&pQ, g_q);
    cudaGetSymbolAddress((void**)&pK, g_k);
    cudaGetSymbolAddress((void**)&pV, g_v);
    cudaGetSymbolAddress((void**)&pL, g_logits);
    cudaGetSymbolAddress((void**)&pAS, g_as);
    cudaGetSymbolAddress((void**)&pBS, g_bs);
    cudaGetSymbolAddress((void**)&pWS, g_ws);

    cudaFuncSetAttribute(attn_kernel, cudaFuncAttributeMaxDynamicSharedMemorySize, ATTN_SMEM);
    cudaFuncSetAttribute(hgemm_kernel<0>, cudaFuncAttributeMaxDynamicSharedMemorySize, GEMM_SMEM);
    cudaFuncSetAttribute(hgemm_kernel<1>, cudaFuncAttributeMaxDynamicSharedMemorySize, GEMM_SMEM);
    cudaFuncSetAttribute(hgemm_kernel<2>, cudaFuncAttributeMaxDynamicSharedMemorySize, GEMM_SMEM);

    dim3 wtThreads(32, 8);

    // patch embedding
    patchify_kernel<<<(PTOT * DIM + 255) / 256, 256>>>(images, pP);
    splitA_kernel<<<((PTOT * DIM / 4) + 255) / 256, 256>>>(pP, pBS, PTOT, DIM);
    splitWT_kernel<<<dim3(DIM / 32, DIM / 32), wtThreads>>>(Wp, pWS, DIM, DIM);
    hgemm_kernel<0><<<dim3(6, 49), 256, GEMM_SMEM>>>(pBS, pWS, bp, pH, nullptr, PTOT, DIM, DIM);
    assemble_kernel<<<(RTOT * DIM + 255) / 256, 256>>>(pH, cls, pos, pX);

    for (int l = 0; l < LL; l++) {
        ln_kernel<0><<<RTOT, 256>>>(pX, ln1_g + l * DIM, ln1_b + l * DIM, pH, nullptr);
        qkv_kernel<<<dim3((RTOT + 63) / 64, NHD), 256>>>(
            pH,
            Wq + (size_t)l * NHD * HDD * HDD, bq + (size_t)l * NHD * HDD,
            Wk + (size_t)l * NHD * HDD * HDD, bk + (size_t)l * NHD * HDD,
            Wv + (size_t)l * NHD * HDD * HDD, bv + (size_t)l * NHD * HDD,
            pQ, pK, pV);
        attn_kernel<<<BB * NHD, 256, ATTN_SMEM>>>(pQ, pK, pV, pX);
        // ln2 writes split fp16 directly (MLP1 A input)
        ln_kernel<1><<<RTOT, 256>>>(pX, ln2_g + l * DIM, ln2_b + l * DIM, nullptr, pBS);

        // MLP1: gelu epilogue writes split fp16 directly (MLP2 A input)
        splitWT_kernel<<<dim3(MLPD / 32, DIM / 32), wtThreads>>>(W1 + (size_t)l * DIM * MLPD, pWS, DIM, MLPD);
        hgemm_kernel<1><<<dim3(24, 50), 256, GEMM_SMEM>>>(pBS, pWS, b1 + (size_t)l * MLPD,
                                                          nullptr, pAS, RTOT, MLPD, DIM);
        // MLP2: + residual into pX
        splitWT_kernel<<<dim3(DIM / 32, MLPD / 32), wtThreads>>>(W2 + (size_t)l * MLPD * DIM, pWS, MLPD, DIM);
        hgemm_kernel<2><<<dim3(6, 50), 256, GEMM_SMEM>>>(pAS, pWS, b2 + (size_t)l * DIM,
                                                         pX, nullptr, RTOT, DIM, MLPD);
    }

    // classifier head on CLS token (row stride = S*D)
    sgemm_kernel<0><<<dim3(8, 1), 256>>>(pX, Wh, bh, pL, BB, NCLS, DIM, SS * DIM);
    softmax_out_kernel<<<BB, 256>>>(pL, out);
}

// round 11
// speedup vs baseline: 1.1921x; 1.0627x over previous
#include <cuda_runtime.h>
#include <cuda_fp16.h>
#include <math.h>
#include <cstdint>

#define BB 32
#define CC 3
#define IMGSZ 224
#define NP 14
#define PS 16
#define DIM 768
#define NHD 12
#define HDD 64
#define LL 12
#define NCLS 1000
#define SS 197
#define MLPD 3072
#define RTOT (BB*SS)      /* 6304 rows */
#define PTOT (BB*NP*NP)   /* 6272 patch rows */

// ---------------- scratch (device globals; no allocations) ----------------
__device__ float g_patches[PTOT*DIM];
__device__ float g_x[RTOT*DIM];
__device__ float g_h[RTOT*DIM];
__device__ float g_q[RTOT*DIM];
__device__ float g_k[RTOT*DIM];
__device__ float g_v[RTOT*DIM];
__device__ float g_logits[BB*NCLS];
__device__ __half g_as[(size_t)RTOT*2*MLPD];     // split MLP hidden [M, 2*MLPD]
__device__ __half g_bs[(size_t)RTOT*2*DIM];      // split D-wide activations [M, 2*DIM]
__device__ __half g_ws[(size_t)MLPD*2*DIM];      // split transposed weights [N, 2K] max
__device__ __half g_wqkv[3*NHD*64*128];          // split qkv weights [3][NH][64 out][hi64|lo64]

#define CP_ASYNC16(dst, src) \
    asm volatile("cp.async.cg.shared.global [%0], [%1], 16;" :: "r"(dst), "l"(src) : "memory")

__device__ __forceinline__ uint32_t smem_u32(const void* p) {
    uint32_t a;
    asm("{ .reg .u64 t; cvta.to.shared.u64 t, %1; cvt.u32.u64 %0, t; }" : "=r"(a) : "l"(p));
    return a;
}

#define MMA16816(c, a, b)                                                        \
    asm volatile("mma.sync.aligned.m16n8k16.row.col.f32.f16.f16.f32 "            \
                 "{%0,%1,%2,%3},{%4,%5,%6,%7},{%8,%9},{%0,%1,%2,%3};"            \
                 : "+f"(c[0]), "+f"(c[1]), "+f"(c[2]), "+f"(c[3])                \
                 : "r"(a[0]), "r"(a[1]), "r"(a[2]), "r"(a[3]), "r"(b[0]), "r"(b[1]));

// ---------------- patchify: (B,C,H,W) -> (B,196,768) ----------------
__global__ void patchify_kernel(const float* __restrict__ img, float* __restrict__ out) {
    int idx = blockIdx.x * blockDim.x + threadIdx.x;
    if (idx >= PTOT * DIM) return;
    int f = idx % DIM;
    int t = (idx / DIM) % (NP * NP);
    int b = idx / (DIM * NP * NP);
    int c  = f >> 8;
    int iy = (f >> 4) & 15;
    int ix = f & 15;
    int py = t / NP, px = t % NP;
    out[idx] = img[(((size_t)b * CC + c) * IMGSZ + py * PS + iy) * IMGSZ + px * PS + ix];
}

// ---------------- assemble x = concat(cls, tokens) + pos ----------------
__global__ void assemble_kernel(const float* __restrict__ tok, const float* __restrict__ cls,
                                const float* __restrict__ pos, float* __restrict__ x) {
    int idx = blockIdx.x * blockDim.x + threadIdx.x;
    if (idx >= RTOT * DIM) return;
    int d = idx % DIM;
    int s = (idx / DIM) % SS;
    int b = idx / (DIM * SS);
    float v = (s == 0) ? cls[d] : tok[((size_t)b * (NP * NP) + (s - 1)) * DIM + d];
    x[idx] = v + pos[s * DIM + d];
}

// ---------------- fp16 split conversions ----------------
__global__ void splitA_kernel(const float* __restrict__ in, __half* __restrict__ out,
                              int M, int K) {
    int i = blockIdx.x * 256 + threadIdx.x;
    int total = (M * K) >> 2;
    if (i >= total) return;
    int e0 = i << 2;
    int m = e0 / K, k = e0 % K;
    float4 v = *(const float4*)(in + e0);
    __half h[4], l[4];
    float vv[4] = {v.x, v.y, v.z, v.w};
#pragma unroll
    for (int j = 0; j < 4; j++) {
        h[j] = __float2half_rn(vv[j]);
        l[j] = __float2half_rn(vv[j] - __half2float(h[j]));
    }
    __half* oh = out + (size_t)m * 2 * K + k;
    *(uint2*)oh         = *(uint2*)h;
    *(uint2*)(oh + K)   = *(uint2*)l;
}

// W: fp32 [K,N] -> fp16 [N,2K] (transpose + split)
__global__ void splitWT_kernel(const float* __restrict__ W, __half* __restrict__ out,
                               int K, int N) {
    __shared__ float t[32][33];
    int n0 = blockIdx.x * 32, k0 = blockIdx.y * 32;
    int tx = threadIdx.x, ty = threadIdx.y;   // 32 x 8
#pragma unroll
    for (int j = 0; j < 32; j += 8)
        t[ty + j][tx] = W[(size_t)(k0 + ty + j) * N + n0 + tx];
    __syncthreads();
#pragma unroll
    for (int j = 0; j < 32; j += 8) {
        float v = t[tx][ty + j];
        __half h = __float2half_rn(v);
        __half l = __float2half_rn(v - __half2float(h));
        size_t base = (size_t)(n0 + ty + j) * 2 * K;
        out[base + k0 + tx]     = h;
        out[base + K + k0 + tx] = l;
    }
}

// qkv weights: Wq/Wk/Wv [NH][64 in][64 out] -> [3][NH][64 out][hi64|lo64]
__global__ void split_wqkv_kernel(const float* __restrict__ Wq, const float* __restrict__ Wk,
                                  const float* __restrict__ Wv, __half* __restrict__ out) {
    int ph = blockIdx.x;                   // 0..35
    int proj = ph / NHD, h = ph % NHD;
    const float* W = (proj == 0 ? Wq : proj == 1 ? Wk : Wv) + (size_t)h * 64 * 64;
    __half* o = out + (size_t)ph * 64 * 128;
    for (int i = threadIdx.x; i < 4096; i += 256) {
        int n = i >> 6, k = i & 63;
        float v = W[k * 64 + n];
        __half hh = __float2half_rn(v);
        o[n * 128 + k]      = hh;
        o[n * 128 + 64 + k] = __float2half_rn(v - __half2float(hh));
    }
}

// ================= fp16 mma.sync 3-pass split GEMM, 2-stage, 2 CTAs/SM (R8/R10 best) =================
#define TSTRIDE 80                 /* bytes per smem row */
#define TILE_B (128 * TSTRIDE)     /* 10240 B per tile */
#define STAGE_B (4 * TILE_B)       /* Ah, Al, Bh, Bl : 40960 B */
#define NSTAGE 2
#define GEMM_SMEM (NSTAGE * STAGE_B)   /* 81920 B -> 2 CTAs/SM */

template<int MODE>
__global__ __launch_bounds__(256, 2)
void hgemm_kernel(const __half* __restrict__ A, const __half* __restrict__ Bw,
                  const float* __restrict__ bias, float* __restrict__ Cf,
                  __half* __restrict__ Ch, int M, int N, int K) {
    extern __shared__ char smc[];
    uint32_t smb = smem_u32(smc);

    int tid = threadIdx.x, lane = tid & 31, warp = tid >> 5;
    int wm = warp & 1, wn = warp >> 1;          // 2 x 4 warps; warp tile 64 x 32
    int g = lane >> 2, q = lane & 3;
    int row0 = blockIdx.y * 128, col0 = blockIdx.x * 128;
    int K2 = 2 * K;

    float c[4][4][4];
#pragma unroll
    for (int mi = 0; mi < 4; mi++)
#pragma unroll
        for (int ni = 0; ni < 4; ni++)
#pragma unroll
            for (int j = 0; j < 4; j++) c[mi][ni][j] = 0.f;

    int lr = tid >> 1;
    int sg0 = (tid & 1) * 2;
    int garow = row0 + lr; if (garow >= M) garow = M - 1;
    const __half* aRow = A + (size_t)garow * K2;
    const __half* bRow = Bw + (size_t)(col0 + lr) * K2;
    uint32_t dOff = lr * TSTRIDE;

    auto load_chunk = [&](int ck) {
        uint32_t base = smb + (uint32_t)(ck & 1) * STAGE_B;
        int k0 = ck * 32;
#pragma unroll
        for (int s = 0; s < 2; s++) {
            int seg = sg0 + s;
            uint32_t d = dOff + seg * 16;
            int srcO = k0 + seg * 8;
            CP_ASYNC16(base + d,              aRow + srcO);          // Ah
            CP_ASYNC16(base + TILE_B + d,     aRow + K + srcO);      // Al
            CP_ASYNC16(base + 2 * TILE_B + d, bRow + srcO);          // Bh
            CP_ASYNC16(base + 3 * TILE_B + d, bRow + K + srcO);      // Bl
        }
        asm volatile("cp.async.commit_group;" ::: "memory");
    };

    int nc = K >> 5;
    load_chunk(0);

    for (int ck = 0; ck < nc; ck++) {
        asm volatile("cp.async.wait_group 0;" ::: "memory");
        __syncthreads();
        if (ck + 1 < nc) load_chunk(ck + 1);

        const char* bufA = smc + (size_t)(ck & 1) * STAGE_B;
#pragma unroll
        for (int kk = 0; kk < 2; kk++) {
            uint32_t ah[4][4], al[4][4], bh[4][2], bl[4][2];
#pragma unroll
            for (int mi = 0; mi < 4; mi++) {
                uint32_t o = (uint32_t)(wm * 64 + mi * 16 + g) * TSTRIDE + kk * 32 + q * 4;
                ah[mi][0] = *(const uint32_t*)(bufA + o);
                ah[mi][1] = *(const uint32_t*)(bufA + o + 8 * TSTRIDE);
                ah[mi][2] = *(const uint32_t*)(bufA + o + 16);
                ah[mi][3] = *(const uint32_t*)(bufA + o + 8 * TSTRIDE + 16);
                al[mi][0] = *(const uint32_t*)(bufA + TILE_B + o);
                al[mi][1] = *(const uint32_t*)(bufA + TILE_B + o + 8 * TSTRIDE);
                al[mi][2] = *(const uint32_t*)(bufA + TILE_B + o + 16);
                al[mi][3] = *(const uint32_t*)(bufA + TILE_B + o + 8 * TSTRIDE + 16);
            }
#pragma unroll
            for (int ni = 0; ni < 4; ni++) {
                uint32_t o = (uint32_t)(wn * 32 + ni * 8 + g) * TSTRIDE + kk * 32 + q * 4;
                bh[ni][0] = *(const uint32_t*)(bufA + 2 * TILE_B + o);
                bh[ni][1] = *(const uint32_t*)(bufA + 2 * TILE_B + o + 16);
                bl[ni][0] = *(const uint32_t*)(bufA + 3 * TILE_B + o);
                bl[ni][1] = *(const uint32_t*)(bufA + 3 * TILE_B + o + 16);
            }
#pragma unroll
            for (int mi = 0; mi < 4; mi++)
#pragma unroll
                for (int ni = 0; ni < 4; ni++) {
                    MMA16816(c[mi][ni], ah[mi], bh[ni]);
                    MMA16816(c[mi][ni], ah[mi], bl[ni]);
                    MMA16816(c[mi][ni], al[mi], bh[ni]);
                }
        }
    }

    // ---- epilogue ----
#pragma unroll
    for (int mi = 0; mi < 4; mi++) {
        int r0 = row0 + wm * 64 + mi * 16 + g;
        int r1 = r0 + 8;
#pragma unroll
        for (int ni = 0; ni < 4; ni++) {
            int cI = col0 + wn * 32 + ni * 8 + 2 * q;
            float2 bv = *(const float2*)&bias[cI];
#pragma unroll
            for (int h = 0; h < 2; h++) {
                int r = h ? r1 : r0;
                if (r >= M) continue;
                float v0 = c[mi][ni][h * 2 + 0] + bv.x;
                float v1 = c[mi][ni][h * 2 + 1] + bv.y;
                if (MODE == 1) {
                    v0 = 0.5f * v0 * (1.f + erff(v0 * 0.70710678118654752f));
                    v1 = 0.5f * v1 * (1.f + erff(v1 * 0.70710678118654752f));
                    __half h0 = __float2half_rn(v0);
                    __half h1 = __float2half_rn(v1);
                    __half l0 = __float2half_rn(v0 - __half2float(h0));
                    __half l1 = __float2half_rn(v1 - __half2float(h1));
                    size_t rb = (size_t)r * 2 * N;
                    *(__half2*)&Ch[rb + cI]     = __halves2half2(h0, h1);
                    *(__half2*)&Ch[rb + N + cI] = __halves2half2(l0, l1);
                } else {
                    float2* pc = (float2*)&Cf[(size_t)r * N + cI];
                    if (MODE == 2) {
                        float2 cur = *pc;
                        v0 += cur.x; v1 += cur.y;
                    }
                    *pc = make_float2(v0, v1);
                }
            }
        }
    }
}

// ================= QKV tensor-core kernel: 128x64 tile per (proj,head) =================
#define QTSTR 272   /* bytes per smem row: 128B hi + 128B lo + 16 pad */
#define QKV_SMEM ((128 + 64) * QTSTR)   /* 52224 B */

__global__ __launch_bounds__(256)
void qkv_mma_kernel(const __half* __restrict__ Xg, const __half* __restrict__ Wqkv,
                    const float* __restrict__ bq, const float* __restrict__ bk,
                    const float* __restrict__ bv,
                    float* __restrict__ q, float* __restrict__ k, float* __restrict__ v) {
    extern __shared__ char smc[];
    uint32_t smb = smem_u32(smc);
    const uint32_t WOFF = 128 * QTSTR;

    int tid = threadIdx.x, lane = tid & 31, warp = tid >> 5;
    int g = lane >> 2, qq = lane & 3;
    int wm = warp & 1, wn = warp >> 1;          // warp tile 64 x 16
    int ph = blockIdx.x;
    int proj = ph / NHD, h = ph % NHD;
    int row0 = blockIdx.y * 128;

    // load X tile: 128 rows x (hi 8 + lo 8) 16B segs
    for (int i = tid; i < 128 * 16; i += 256) {
        int r = i >> 4, t = i & 15;
        int half = t >> 3, seg = t & 7;
        int gr = row0 + r; if (gr >= RTOT) gr = RTOT - 1;
        const __half* src = Xg + (size_t)gr * (2 * DIM) + half * DIM + h * 64 + seg * 8;
        CP_ASYNC16(smb + (uint32_t)r * QTSTR + half * 128 + seg * 16, src);
    }
    // load W tile: 64 rows x 16 segs
    for (int i = tid; i < 64 * 16; i += 256) {
        int n = i >> 4, t = i & 15;
        const __half* src = Wqkv + (size_t)ph * 64 * 128 + n * 128 + t * 8;
        CP_ASYNC16(smb + WOFF + (uint32_t)n * QTSTR + t * 16, src);
    }
    asm volatile("cp.async.commit_group;" ::: "memory");
    asm volatile("cp.async.wait_group 0;" ::: "memory");
    __syncthreads();

    float c[4][2][4];
#pragma unroll
    for (int mi = 0; mi < 4; mi++)
#pragma unroll
        for (int ni = 0; ni < 2; ni++)
#pragma unroll
            for (int j = 0; j < 4; j++) c[mi][ni][j] = 0.f;

#pragma unroll
    for (int s = 0; s < 4; s++) {       // 4 k16 steps over K=64
        uint32_t ah[4][4], al[4][4], bh[2][2], bl[2][2];
#pragma unroll
        for (int mi = 0; mi < 4; mi++) {
            uint32_t o = (uint32_t)(wm * 64 + mi * 16 + g) * QTSTR + s * 32 + qq * 4;
            ah[mi][0] = *(const uint32_t*)(smc + o);
            ah[mi][1] = *(const uint32_t*)(smc + o + 8 * QTSTR);
            ah[mi][2] = *(const uint32_t*)(smc + o + 16);
            ah[mi][3] = *(const uint32_t*)(smc + o + 8 * QTSTR + 16);
            al[mi][0] = *(const uint32_t*)(smc + o + 128);
            al[mi][1] = *(const uint32_t*)(smc + o + 8 * QTSTR + 128);
            al[mi][2] = *(const uint32_t*)(smc + o + 144);
            al[mi][3] = *(const uint32_t*)(smc + o + 8 * QTSTR + 144);
        }
#pragma unroll
        for (int ni = 0; ni < 2; ni++) {
            uint32_t o = WOFF + (uint32_t)(wn * 16 + ni * 8 + g) * QTSTR + s * 32 + qq * 4;
            bh[ni][0] = *(const uint32_t*)(smc + o);
            bh[ni][1] = *(const uint32_t*)(smc + o + 16);
            bl[ni][0] = *(const uint32_t*)(smc + o + 128);
            bl[ni][1] = *(const uint32_t*)(smc + o + 144);
        }
#pragma unroll
        for (int mi = 0; mi < 4; mi++)
#pragma unroll
            for (int ni = 0; ni < 2; ni++) {
                MMA16816(c[mi][ni], ah[mi], bh[ni]);
                MMA16816(c[mi][ni], ah[mi], bl[ni]);
                MMA16816(c[mi][ni], al[mi], bh[ni]);
            }
    }

    const float* bias = (proj == 0 ? bq : proj == 1 ? bk : bv) + h * 64;
    float* outp = (proj == 0 ? q : proj == 1 ? k : v);
#pragma unroll
    for (int mi = 0; mi < 4; mi++) {
        int r0 = row0 + wm * 64 + mi * 16 + g;
#pragma unroll
        for (int ni = 0; ni < 2; ni++) {
            int n = wn * 16 + ni * 8 + 2 * qq;
            float2 bv2 = *(const float2*)&bias[n];
#pragma unroll
            for (int h2 = 0; h2 < 2; h2++) {
                int r = h2 ? r0 + 8 : r0;
                if (r >= RTOT) continue;
                int b = r / SS, sI = r % SS;
                float* dst = outp + (((size_t)b * NHD + h) * SS + sI) * HDD + n;
                dst[0] = c[mi][ni][h2 * 2 + 0] + bv2.x;
                dst[1] = c[mi][ni][h2 * 2 + 1] + bv2.y;
            }
        }
    }
}

// ---------------- fp32 SGEMM (tiny classifier head) ----------------
template<int MODE>
__global__ void sgemm_kernel(const float* __restrict__ A, const float* __restrict__ B,
                             const float* __restrict__ bias, float* __restrict__ C,
                             int M, int N, int K, int lda) {
    __shared__ float As[8][128];
    __shared__ float Bs[8][128];
    int tid = threadIdx.x;
    int tx = tid & 15, ty = tid >> 4;
    int row0 = blockIdx.y * 128, col0 = blockIdx.x * 128;
    int arow = tid >> 1, acol = (tid & 1) * 4;
    int brow = tid >> 5, bcol = (tid & 31) * 4;

    float acc[8][8];
#pragma unroll
    for (int i = 0; i < 8; i++)
#pragma unroll
        for (int j = 0; j < 8; j++) acc[i][j] = 0.f;

    for (int k0 = 0; k0 < K; k0 += 8) {
        float4 av = make_float4(0.f, 0.f, 0.f, 0.f);
        if (row0 + arow < M)
            av = *(const float4*)(A + (size_t)(row0 + arow) * lda + k0 + acol);
        As[acol + 0][arow] = av.x;
        As[acol + 1][arow] = av.y;
        As[acol + 2][arow] = av.z;
        As[acol + 3][arow] = av.w;

        int bc = col0 + bcol;
        float4 bv = make_float4(0.f, 0.f, 0.f, 0.f);
        if (bc + 3 < N) {
            bv = *(const float4*)(B + (size_t)(k0 + brow) * N + bc);
        } else {
            float tmp[4] = {0.f, 0.f, 0.f, 0.f};
            for (int i = 0; i < 4; i++)
                if (bc + i < N) tmp[i] = B[(size_t)(k0 + brow) * N + bc + i];
            bv = make_float4(tmp[0], tmp[1], tmp[2], tmp[3]);
        }
        *(float4*)&Bs[brow][bcol] = bv;
        __syncthreads();

#pragma unroll
        for (int kk = 0; kk < 8; kk++) {
            float a[8], bb[8];
#pragma unroll
            for (int i = 0; i < 8; i++) a[i] = As[kk][ty * 8 + i];
#pragma unroll
            for (int j = 0; j < 8; j++) bb[j] = Bs[kk][tx * 8 + j];
#pragma unroll
            for (int i = 0; i < 8; i++)
#pragma unroll
                for (int j = 0; j < 8; j++) acc[i][j] = fmaf(a[i], bb[j], acc[i][j]);
        }
        __syncthreads();
    }

#pragma unroll
    for (int i = 0; i < 8; i++) {
        int r = row0 + ty * 8 + i;
        if (r >= M) continue;
#pragma unroll
        for (int j = 0; j < 8; j++) {
            int cI = col0 + tx * 8 + j;
            if (cI >= N) continue;
            float v = acc[i][j] + bias[cI];
            if (MODE == 1) v = 0.5f * v * (1.f + erff(v * 0.70710678118654752f));
            if (MODE == 2) v += C[(size_t)r * N + cI];
            C[(size_t)r * N + cI] = v;
        }
    }
}

// ---------------- LayerNorm over D=768 ----------------
template<int SPLIT>
__global__ void ln_kernel(const float* __restrict__ x, const float* __restrict__ g,
                          const float* __restrict__ be, float* __restrict__ o,
                          __half* __restrict__ oh) {
    int row = blockIdx.x, tid = threadIdx.x;
    const float* xr = x + (size_t)row * DIM;
    float v0 = xr[tid], v1 = xr[tid + 256], v2 = xr[tid + 512];
    __shared__ float red[32];
    int lane = tid & 31, w = tid >> 5;

    float s = v0 + v1 + v2;
#pragma unroll
    for (int off = 16; off; off >>= 1) s += __shfl_xor_sync(0xffffffffu, s, off);
    if (lane == 0) red[w] = s;
    __syncthreads();
    float tot = (lane < 8) ? red[lane] : 0.f;
#pragma unroll
    for (int off = 16; off; off >>= 1) tot += __shfl_xor_sync(0xffffffffu, tot, off);
    float mean = tot * (1.f / 768.f);

    float d0 = v0 - mean, d1 = v1 - mean, d2 = v2 - mean;
    float sq = d0 * d0 + d1 * d1 + d2 * d2;
#pragma unroll
    for (int off = 16; off; off >>= 1) sq += __shfl_xor_sync(0xffffffffu, sq, off);
    __syncthreads();
    if (lane == 0) red[w] = sq;
    __syncthreads();
    float tot2 = (lane < 8) ? red[lane] : 0.f;
#pragma unroll
    for (int off = 16; off; off >>= 1) tot2 += __shfl_xor_sync(0xffffffffu, tot2, off);
    float inv = rsqrtf(tot2 * (1.f / 768.f) + 1e-5f);

    float r0 = d0 * inv * g[tid]       + be[tid];
    float r1 = d1 * inv * g[tid + 256] + be[tid + 256];
    float r2 = d2 * inv * g[tid + 512] + be[tid + 512];
    if (SPLIT == 0) {
        float* orow = o + (size_t)row * DIM;
        orow[tid] = r0; orow[tid + 256] = r1; orow[tid + 512] = r2;
    } else {
        __half* orow = oh + (size_t)row * 2 * DIM;
        float vv[3] = {r0, r1, r2};
        int dd[3] = {tid, tid + 256, tid + 512};
#pragma unroll
        for (int j = 0; j < 3; j++) {
            __half h = __float2half_rn(vv[j]);
            orow[dd[j]]       = h;
            orow[DIM + dd[j]] = __float2half_rn(vv[j] - __half2float(h));
        }
    }
}

// ---------------- fused attention: one CTA per (b,h); K/V loaded ONCE ----------------
#define KS_STRIDE 208
#define SC_STRIDE 208
#define ATTN_SMEM ((64*KS_STRIDE + SS*HDD + 64*32 + 32*SC_STRIDE) * 4)

__global__ void attn_kernel(const float* __restrict__ q, const float* __restrict__ k,
                            const float* __restrict__ v, float* __restrict__ x) {
    extern __shared__ float smf[];
    float* Ks  = smf;
    float* Vs  = Ks + 64 * KS_STRIDE;
    float* Qs  = Vs + SS * HDD;
    float* Ssc = Qs + 64 * 32;

    int bh = blockIdx.x;
    int b = bh / NHD, hh = bh % NHD;
    int tid = threadIdx.x;
    int lane = tid & 31, w = tid >> 5;

    const float* kb = k + (size_t)bh * SS * HDD;
    const float* vb = v + (size_t)bh * SS * HDD;
    const float* qb = q + (size_t)bh * SS * HDD;

    for (int i = tid; i < 64 * KS_STRIDE; i += 256) Ks[i] = 0.f;
    __syncthreads();
    for (int i = tid; i < SS * HDD; i += 256) {
        int t = i >> 6, e = i & 63;
        Ks[e * KS_STRIDE + t] = kb[i];
        Vs[i] = vb[i];
    }
    __syncthreads();

    for (int qt = 0; qt < (SS + 31) / 32; qt++) {
        for (int i = tid; i < 32 * 64; i += 256) {
            int e = i >> 5, qi = i & 31;
            int s = qt * 32 + qi;
            Qs[e * 32 + qi] = (s < SS) ? qb[(size_t)s * HDD + e] : 0.f;
        }
        __syncthreads();

        int qg = w;
        int kg = lane;
        {
            float acc[4][8];
#pragma unroll
            for (int i = 0; i < 4; i++)
#pragma unroll
                for (int j = 0; j < 8; j++) acc[i][j] = 0.f;
#pragma unroll 8
            for (int e = 0; e < 64; e++) {
                float4 a  = *(float4*)&Qs[e * 32 + qg * 4];
                float4 b0 = *(float4*)&Ks[e * KS_STRIDE + kg * 8];
                float4 b1 = *(float4*)&Ks[e * KS_STRIDE + kg * 8 + 4];
                float av[4] = {a.x, a.y, a.z, a.w};
                float bv8[8] = {b0.x, b0.y, b0.z, b0.w, b1.x, b1.y, b1.z, b1.w};
#pragma unroll
                for (int i = 0; i < 4; i++)
#pragma unroll
                    for (int j = 0; j < 8; j++) acc[i][j] = fmaf(av[i], bv8[j], acc[i][j]);
            }
            for (int i = 0; i < 4; i++)
                for (int j = 0; j < 8; j++) {
                    int t = kg * 8 + j;
                    if (t < SS) Ssc[(qg * 4 + i) * SC_STRIDE + t] = acc[i][j] * 0.125f;
                }
        }
        __syncthreads();

        for (int r = w * 4; r < w * 4 + 4; r++) {
            float mx = -1e30f;
            for (int t = lane; t < SS; t += 32) mx = fmaxf(mx, Ssc[r * SC_STRIDE + t]);
#pragma unroll
            for (int off = 16; off; off >>= 1) mx = fmaxf(mx, __shfl_xor_sync(0xffffffffu, mx, off));
            float sum = 0.f;
            for (int t = lane; t < SS; t += 32) {
                float p = expf(Ssc[r * SC_STRIDE + t] - mx);
                Ssc[r * SC_STRIDE + t] = p;
                sum += p;
            }
#pragma unroll
            for (int off = 16; off; off >>= 1) sum += __shfl_xor_sync(0xffffffffu, sum, off);
            float invs = 1.f / sum;
            for (int t = lane; t < SS; t += 32) Ssc[r * SC_STRIDE + t] *= invs;
        }
        __syncthreads();

        int qg2 = tid >> 4;
        int dg = tid & 15;
        float o0[4] = {0.f, 0.f, 0.f, 0.f}, o1[4] = {0.f, 0.f, 0.f, 0.f};
        int q0 = qg2 * 2;
        for (int t = 0; t < SS; t++) {
            float p0 = Ssc[q0 * SC_STRIDE + t];
            float p1 = Ssc[(q0 + 1) * SC_STRIDE + t];
            float4 vv = *(float4*)&Vs[t * 64 + dg * 4];
            o0[0] = fmaf(p0, vv.x, o0[0]); o0[1] = fmaf(p0, vv.y, o0[1]);
            o0[2] = fmaf(p0, vv.z, o0[2]); o0[3] = fmaf(p0, vv.w, o0[3]);
            o1[0] = fmaf(p1, vv.x, o1[0]); o1[1] = fmaf(p1, vv.y, o1[1]);
            o1[2] = fmaf(p1, vv.z, o1[2]); o1[3] = fmaf(p1, vv.w, o1[3]);
        }
        int s0 = qt * 32 + q0;
        if (s0 < SS) {
            float4* px = (float4*)&x[((size_t)(b * SS + s0)) * DIM + hh * HDD + dg * 4];
            float4 cur = *px;
            cur.x += o0[0]; cur.y += o0[1]; cur.z += o0[2]; cur.w += o0[3];
            *px = cur;
        }
        if (s0 + 1 < SS) {
            float4* px = (float4*)&x[((size_t)(b * SS + s0 + 1)) * DIM + hh * HDD + dg * 4];
            float4 cur = *px;
            cur.x += o1[0]; cur.y += o1[1]; cur.z += o1[2]; cur.w += o1[3];
            *px = cur;
        }
        __syncthreads();
    }
}

// ---------------- final softmax over 1000 classes ----------------
__global__ void softmax_out_kernel(const float* __restrict__ logits, float* __restrict__ out) {
    int b = blockIdx.x, tid = threadIdx.x;
    int lane = tid & 31, w = tid >> 5;
    __shared__ float red[32];
    const float* lr = logits + (size_t)b * NCLS;

    float mx = -1e30f;
    for (int i = tid; i < NCLS; i += 256) mx = fmaxf(mx, lr[i]);
#pragma unroll
    for (int off = 16; off; off >>= 1) mx = fmaxf(mx, __shfl_xor_sync(0xffffffffu, mx, off));
    if (lane == 0) red[w] = mx;
    __syncthreads();
    float gm = (lane < 8) ? red[lane] : -1e30f;
#pragma unroll
    for (int off = 16; off; off >>= 1) gm = fmaxf(gm, __shfl_xor_sync(0xffffffffu, gm, off));

    float sum = 0.f;
    for (int i = tid; i < NCLS; i += 256) sum += expf(lr[i] - gm);
#pragma unroll
    for (int off = 16; off; off >>= 1) sum += __shfl_xor_sync(0xffffffffu, sum, off);
    __syncthreads();
    if (lane == 0) red[w] = sum;
    __syncthreads();
    float gs = (lane < 8) ? red[lane] : 0.f;
#pragma unroll
    for (int off = 16; off; off >>= 1) gs += __shfl_xor_sync(0xffffffffu, gs, off);
    float invs = 1.f / gs;

    for (int i = tid; i < NCLS; i += 256) out[(size_t)b * NCLS + i] = expf(lr[i] - gm) * invs;
}

// ---------------- launch ----------------
extern "C" void kernel_launch(void* const* d_in, const int* in_sizes, int n_in,
                              void* d_out, int out_size) {
    const float* images = (const float*)d_in[0];
    const float* Wp  = (const float*)d_in[1];
    const float* bp  = (const float*)d_in[2];
    const float* cls = (const float*)d_in[3];
    const float* pos = (const float*)d_in[4];
    const float* ln1_g = (const float*)d_in[5];
    const float* ln1_b = (const float*)d_in[6];
    const float* Wq = (const float*)d_in[7];
    const float* bq = (const float*)d_in[8];
    const float* Wk = (const float*)d_in[9];
    const float* bk = (const float*)d_in[10];
    const float* Wv = (const float*)d_in[11];
    const float* bv = (const float*)d_in[12];
    const float* ln2_g = (const float*)d_in[13];
    const float* ln2_b = (const float*)d_in[14];
    const float* W1 = (const float*)d_in[15];
    const float* b1 = (const float*)d_in[16];
    const float* W2 = (const float*)d_in[17];
    const float* b2 = (const float*)d_in[18];
    const float* Wh = (const float*)d_in[19];
    const float* bh = (const float*)d_in[20];
    float* out = (float*)d_out;

    float *pP, *pX, *pH, *pQ, *pK, *pV, *pL;
    __half *pAS, *pBS, *pWS, *pWQ;
    cudaGetSymbolAddress((void**)&pP, g_patches);
    cudaGetSymbolAddress((void**)&pX, g_x);
    cudaGetSymbolAddress((void**)&pH, g_h);
    cudaGetSymbolAddress((void**)&pQ, g_q);
    cudaGetSymbolAddress((void**)&pK, g_k);
    cudaGetSymbolAddress((void**)&pV, g_v);
    cudaGetSymbolAddress((void**)&pL, g_logits);
    cudaGetSymbolAddress((void**)&pAS, g_as);
    cudaGetSymbolAddress((void**)&pBS, g_bs);
    cudaGetSymbolAddress((void**)&pWS, g_ws);
    cudaGetSymbolAddress((void**)&pWQ, g_wqkv);

    cudaFuncSetAttribute(attn_kernel, cudaFuncAttributeMaxDynamicSharedMemorySize, ATTN_SMEM);
    cudaFuncSetAttribute(hgemm_kernel<0>, cudaFuncAttributeMaxDynamicSharedMemorySize, GEMM_SMEM);
    cudaFuncSetAttribute(hgemm_kernel<1>, cudaFuncAttributeMaxDynamicSharedMemorySize, GEMM_SMEM);
    cudaFuncSetAttribute(hgemm_kernel<2>, cudaFuncAttributeMaxDynamicSharedMemorySize, GEMM_SMEM);
    cudaFuncSetAttribute(qkv_mma_kernel, cudaFuncAttributeMaxDynamicSharedMemorySize, QKV_SMEM);

    dim3 wtThreads(32, 8);

    // patch embedding
    patchify_kernel<<<(PTOT * DIM + 255) / 256, 256>>>(images, pP);
    splitA_kernel<<<((PTOT * DIM / 4) + 255) / 256, 256>>>(pP, pBS, PTOT, DIM);
    splitWT_kernel<<<dim3(DIM / 32, DIM / 32), wtThreads>>>(Wp, pWS, DIM, DIM);
    hgemm_kernel<0><<<dim3(6, 49), 256, GEMM_SMEM>>>(pBS, pWS, bp, pH, nullptr, PTOT, DIM, DIM);
    assemble_kernel<<<(RTOT * DIM + 255) / 256, 256>>>(pH, cls, pos, pX);

    for (int l = 0; l < LL; l++) {
        // ln1 writes split fp16 (QKV A input)
        ln_kernel<1><<<RTOT, 256>>>(pX, ln1_g + l * DIM, ln1_b + l * DIM, nullptr, pBS);
        split_wqkv_kernel<<<36, 256>>>(Wq + (size_t)l * NHD * HDD * HDD,
                                       Wk + (size_t)l * NHD * HDD * HDD,
                                       Wv + (size_t)l * NHD * HDD * HDD, pWQ);
        qkv_mma_kernel<<<dim3(36, (RTOT + 127) / 128), 256, QKV_SMEM>>>(
            pBS, pWQ,
            bq + (size_t)l * NHD * HDD, bk + (size_t)l * NHD * HDD, bv + (size_t)l * NHD * HDD,
            pQ, pK, pV);
        attn_kernel<<<BB * NHD, 256, ATTN_SMEM>>>(pQ, pK, pV, pX);
        // ln2 writes split fp16 (MLP1 A input)
        ln_kernel<1><<<RTOT, 256>>>(pX, ln2_g + l * DIM, ln2_b + l * DIM, nullptr, pBS);

        // MLP1: gelu epilogue writes split fp16 (MLP2 A input)
        splitWT_kernel<<<dim3(MLPD / 32, DIM / 32), wtThreads>>>(W1 + (size_t)l * DIM * MLPD, pWS, DIM, MLPD);
        hgemm_kernel<1><<<dim3(24, 50), 256, GEMM_SMEM>>>(pBS, pWS, b1 + (size_t)l * MLPD,
                                                          nullptr, pAS, RTOT, MLPD, DIM);
        // MLP2: + residual into pX
        splitWT_kernel<<<dim3(DIM / 32, MLPD / 32), wtThreads>>>(W2 + (size_t)l * MLPD * DIM, pWS, MLPD, DIM);
        hgemm_kernel<2><<<dim3(6, 50), 256, GEMM_SMEM>>>(pAS, pWS, b2 + (size_t)l * DIM,
                                                         pX, nullptr, RTOT, DIM, MLPD);
    }

    // classifier head on CLS token (row stride = S*D)
    sgemm_kernel<0><<<dim3(8, 1), 256>>>(pX, Wh, bh, pL, BB, NCLS, DIM, SS * DIM);
    softmax_out_kernel<<<BB, 256>>>(pL, out);
}